// round 15
// baseline (speedup 1.0000x reference)
#include <cuda_runtime.h>
#include <stdint.h>
#include <math.h>

// ---------------- geometry ----------------
// x      : [128,  1, 128, 128]
// h1b    : [128, 4096hw, 32ci]   conv1 + relu -> bf16         (g_h1b)
// h2b    : [128, 1024hw, 64ci]   conv2 (bf16 mma) -> bf16     (g_h2b)
// z      : [128, 64,  32,  32]   conv3 (bf16 mma) [tf32]      (g_z)
// zqb    : [128, 1024hw, 64ci]   codebook gather -> bf16      (g_zqb)
// d1b    : [128, 1024hw, 64ci]   deconv1 (bf16 mma) -> bf16   (g_d1b)
// d2     : [128, 32,  64,  64]   deconv2 (bf16 mma) fp32      (g_h1)
// x_rec  : [128,  1, 128, 128]   -> d_out[0 : 2097152]
// d_out[2097152] = recon_loss, d_out[2097153] = vq_loss

#define N_XREC   2097152
#define N_Z      8388608

__device__ float    g_h1[128 * 32 * 64 * 64];
__device__ float    g_z [128 * 64 * 32 * 32];
__device__ uint32_t g_h1b[128 * 4096 * 16];
__device__ uint32_t g_h2b[128 * 1024 * 32];
__device__ uint32_t g_zqb[128 * 1024 * 32];
__device__ uint32_t g_d1b[128 * 1024 * 32];
// bf16x2 3x3 weights: [set][sl(4)][tap(9)][kp(8)][72]
__device__ uint32_t g_wtb[2 * 20736];
// bf16x2 conv2 weights: [tap(16)][kp(16)][72]
__device__ uint32_t g_w2b[18432];
// bf16x2 deconv2 weights: [ks(4)][par(4)][tap(4)][kpin(8)][40]
__device__ uint32_t g_wd2b[20480];
// tf32-rounded codebook: [k(64)][136]
__device__ float g_cbt[8704];

// ---------------- cp.async helpers ----------------
__device__ __forceinline__ void cp4(uint32_t dst, const float* src, bool p) {
    asm volatile("cp.async.ca.shared.global [%0], [%1], 4, %2;"
                 :: "r"(dst), "l"(src), "r"(p ? 4u : 0u));
}
__device__ __forceinline__ void cp8z(uint32_t dst, const void* src, bool p) {
    asm volatile("cp.async.ca.shared.global [%0], [%1], 8, %2;"
                 :: "r"(dst), "l"(src), "r"(p ? 8u : 0u));
}
__device__ __forceinline__ void cp16(uint32_t dst, const void* src) {
    asm volatile("cp.async.ca.shared.global [%0], [%1], 16;"
                 :: "r"(dst), "l"(src));
}
__device__ __forceinline__ void cp16z(uint32_t dst, const void* src, bool p) {
    asm volatile("cp.async.ca.shared.global [%0], [%1], 16, %2;"
                 :: "r"(dst), "l"(src), "r"(p ? 16u : 0u));
}
__device__ __forceinline__ void cp_commit() {
    asm volatile("cp.async.commit_group;");
}
__device__ __forceinline__ void cp_wait1() {
    asm volatile("cp.async.wait_group 1;");
}
__device__ __forceinline__ void cp_wait0() {
    asm volatile("cp.async.wait_group 0;");
}

// ---------------- mma helpers ----------------
__device__ __forceinline__ uint32_t f2tf(float f) {
    uint32_t r; asm("cvt.rna.tf32.f32 %0, %1;" : "=r"(r) : "f"(f)); return r;
}
__device__ __forceinline__ float f2tf_f(float f) {
    uint32_t r = f2tf(f); return __uint_as_float(r);
}
__device__ __forceinline__ uint32_t pk_bf16(float lo, float hi) {
    uint32_t r; asm("cvt.rn.bf16x2.f32 %0, %1, %2;" : "=r"(r) : "f"(hi), "f"(lo));
    return r;
}
__device__ __forceinline__ void mma_tf32(float& d0, float& d1, float& d2, float& d3,
                                         uint32_t a0, uint32_t a1, uint32_t a2, uint32_t a3,
                                         uint32_t b0, uint32_t b1) {
    asm volatile("mma.sync.aligned.m16n8k8.row.col.f32.tf32.tf32.f32 "
                 "{%0,%1,%2,%3}, {%4,%5,%6,%7}, {%8,%9}, {%0,%1,%2,%3};"
                 : "+f"(d0), "+f"(d1), "+f"(d2), "+f"(d3)
                 : "r"(a0), "r"(a1), "r"(a2), "r"(a3), "r"(b0), "r"(b1));
}
__device__ __forceinline__ void mma_bf16(float& d0, float& d1, float& d2, float& d3,
                                         uint32_t a0, uint32_t a1, uint32_t a2, uint32_t a3,
                                         uint32_t b0, uint32_t b1) {
    asm volatile("mma.sync.aligned.m16n8k16.row.col.f32.bf16.bf16.f32 "
                 "{%0,%1,%2,%3}, {%4,%5,%6,%7}, {%8,%9}, {%0,%1,%2,%3};"
                 : "+f"(d0), "+f"(d1), "+f"(d2), "+f"(d3)
                 : "r"(a0), "r"(a1), "r"(a2), "r"(a3), "r"(b0), "r"(b1));
}

// ---------------- merged prep ----------------
__global__ void __launch_bounds__(256) prep_all_k(const float* __restrict__ w3,
                                                  const float* __restrict__ dw1,
                                                  const float* __restrict__ w2,
                                                  const float* __restrict__ dw2,
                                                  const float* __restrict__ cb,
                                                  float* out) {
    int i = blockIdx.x * 256 + threadIdx.x;
    if (i < 2) { out[N_XREC + i] = 0.0f; }
    if (i < 41472) {
        int set = i / 20736, r = i - set * 20736;
        int o = r % 72, q = r / 72;
        int kp = q & 7, q2 = q >> 3;
        int tap = q2 % 9, sl = q2 / 9;
        int ci0 = sl * 16 + 2 * kp;
        float v0 = 0.0f, v1 = 0.0f;
        if (o < 64) {
            if (set) {
                v0 = dw1[(ci0 * 64 + o) * 9 + (8 - tap)];
                v1 = dw1[((ci0 + 1) * 64 + o) * 9 + (8 - tap)];
            } else {
                v0 = w3[(o * 64 + ci0) * 9 + tap];
                v1 = w3[(o * 64 + ci0 + 1) * 9 + tap];
            }
        }
        g_wtb[i] = pk_bf16(v0, v1);
    } else if (i < 59904) {
        int j = i - 41472;
        int o = j % 72, q = j / 72;
        int kp = q & 15, tap = q >> 4;
        int ci0 = 2 * kp;
        float v0 = 0.0f, v1 = 0.0f;
        if (o < 64) {
            v0 = w2[(o * 32 + ci0) * 16 + tap];
            v1 = w2[(o * 32 + ci0 + 1) * 16 + tap];
        }
        g_w2b[j] = pk_bf16(v0, v1);
    } else if (i < 80384) {
        // g_wd2b idx = (((ks*4 + par)*4 + tap)*8 + kpin)*40 + o ; kp = ks*8+kpin
        int j = i - 59904;
        int o = j % 40, q = j / 40;
        int kpin = q & 7, q2 = q >> 3;
        int tap = q2 & 3, q3 = q2 >> 2;
        int par = q3 & 3, ks = q3 >> 2;
        int kp = ks * 8 + kpin;
        int py = par >> 1, px = par & 1;
        int ky = (1 - py) + 2 * (tap >> 1);
        int kx = (1 - px) + 2 * (tap & 1);
        int ci0 = 2 * kp;
        float v0 = 0.0f, v1 = 0.0f;
        if (o < 32) {
            v0 = dw2[(ci0 * 32 + o) * 16 + ky * 4 + kx];
            v1 = dw2[((ci0 + 1) * 32 + o) * 16 + ky * 4 + kx];
        }
        g_wd2b[j] = pk_bf16(v0, v1);
    } else if (i < 89088) {
        int j = i - 80384;
        int m = j % 136, k = j / 136;
        float v = 0.0f;
        if (m < 128) v = cb[m * 64 + k];
        g_cbt[j] = f2tf_f(v);
    }
}

// ---------------- conv1: 1->32, k4 s2 p1, relu; output bf16 [hw][ci] ----------------
__global__ void __launch_bounds__(256) conv1_k(const float* __restrict__ x,
                                               const float* __restrict__ w,
                                               const float* __restrict__ b) {
    __shared__ float tin[10][132];
    __shared__ float ws[512];
    __shared__ float bs[32];
    int n = blockIdx.x >> 4, y0 = (blockIdx.x & 15) * 4;
    int t = threadIdx.x;
    int xo = t & 63, ys = t >> 6, yo = y0 + ys;
    for (int i = t; i < 512; i += 256) ws[i] = w[i];
    if (t < 32) bs[t] = b[t];
    const float* xp = x + n * 16384;
    for (int j = t; j < 1320; j += 256) {
        int r = j / 132, c = j - r * 132;
        int iy = 2 * y0 - 1 + r, ix = c - 1;
        float v = 0.0f;
        if ((unsigned)iy < 128u && (unsigned)ix < 128u) v = xp[iy * 128 + ix];
        tin[r][c] = v;
    }
    __syncthreads();

    float xin[16];
#pragma unroll
    for (int ky = 0; ky < 4; ky++)
#pragma unroll
        for (int kx = 0; kx < 4; kx++)
            xin[ky * 4 + kx] = tin[2 * ys + ky][2 * xo + kx];

    float acc[32];
#pragma unroll 4
    for (int o = 0; o < 32; o++) {
        float a = bs[o];
#pragma unroll
        for (int k = 0; k < 16; k++) a = fmaf(xin[k], ws[o * 16 + k], a);
        acc[o] = fmaxf(a, 0.0f);
    }
    uint32_t pk[16];
#pragma unroll
    for (int j = 0; j < 16; j++) pk[j] = pk_bf16(acc[2 * j], acc[2 * j + 1]);
    uint4* op = (uint4*)(g_h1b + (n * 4096 + yo * 64 + xo) * 16);
#pragma unroll
    for (int q = 0; q < 4; q++)
        op[q] = make_uint4(pk[4 * q], pk[4 * q + 1], pk[4 * q + 2], pk[4 * q + 3]);
}

// ---------------- conv2: 32->64, k4 s2 p1, relu — bf16 mma, chunked weights ------
// smem u32: tinb[6*66 pix][18] (7128) + ws[2][2tap*16kp][72] (2*2304) = 46944 B
__global__ void __launch_bounds__(256) conv2b_k(const float* __restrict__ b) {
    extern __shared__ float dsm[];
    uint32_t* tinb = (uint32_t*)dsm;
    uint32_t* ws   = (uint32_t*)dsm + 7128;
    uint32_t tin_s = (uint32_t)__cvta_generic_to_shared(tinb);
    uint32_t ws_s  = (uint32_t)__cvta_generic_to_shared(ws);
    int n = blockIdx.x >> 4, y0 = (blockIdx.x & 15) * 2;
    int t = threadIdx.x;
    int wid = t >> 5, lane = t & 31;
    int g = lane >> 2, tg = lane & 3;
    int obase = (wid & 3) * 16;
    int nbase = (wid >> 2) * 32;
    int o_lo = obase + g, o_hi = o_lo + 8;
    const uint32_t* in0 = g_h1b + n * 65536;

    int boff[4];
#pragma unroll
    for (int nt = 0; nt < 4; nt++) {
        int p = nbase + nt * 8 + g;
        boff[nt] = (p >> 5) * 132 + (p & 31) * 2;
    }

    float acc[4][4];
#pragma unroll
    for (int nt = 0; nt < 4; nt++)
#pragma unroll
        for (int j = 0; j < 4; j++) acc[nt][j] = 0.0f;

    // prologue: tile (8B copies) + first weight chunk
    for (int j = t; j < 3168; j += 256) {
        int pix = j >> 3, q = j & 7;
        int r = pix / 66, c = pix - r * 66;
        int iy = 2 * y0 - 1 + r, ix = c - 1;
        bool p = ((unsigned)iy < 64u) & ((unsigned)ix < 64u);
        const uint32_t* src = in0 + (p ? (iy * 64 + ix) * 16 : 0) + q * 2;
        cp8z(tin_s + ((r * 66 + c) * 18 + q * 2) * 4, src, p);
    }
    auto load_ws = [&](int buf, int c) {
        const uint32_t* src = g_w2b + c * 2304;
        for (int j = t; j < 576; j += 256)
            cp16(ws_s + (buf * 2304 + j * 4) * 4, src + j * 4);
        cp_commit();
    };
    load_ws(0, 0);

    for (int c = 0; c < 8; c++) {
        if (c < 7) { load_ws((c + 1) & 1, c + 1); cp_wait1(); }
        else       { cp_wait0(); }
        __syncthreads();
        const uint32_t* wb = ws + (c & 1) * 2304;
#pragma unroll
        for (int tl = 0; tl < 2; tl++) {
            int tt = c * 2 + tl;
            int ky = tt >> 2, kx = tt & 3;
            int doff = ky * 66 + kx;
#pragma unroll
            for (int ks = 0; ks < 2; ks++) {
                const uint32_t* wpb = wb + tl * 1152 + ks * 8 * 72;
                uint32_t ra0 = wpb[tg * 72 + o_lo];
                uint32_t ra1 = wpb[tg * 72 + o_hi];
                uint32_t ra2 = wpb[(tg + 4) * 72 + o_lo];
                uint32_t ra3 = wpb[(tg + 4) * 72 + o_hi];
#pragma unroll
                for (int nt = 0; nt < 4; nt++) {
                    const uint32_t* tp = tinb + (boff[nt] + doff) * 18 + ks * 8;
                    uint32_t rb0 = tp[tg];
                    uint32_t rb1 = tp[tg + 4];
                    mma_bf16(acc[nt][0], acc[nt][1], acc[nt][2], acc[nt][3],
                             ra0, ra1, ra2, ra3, rb0, rb1);
                }
            }
        }
        __syncthreads();
    }

    float bv_lo = b[o_lo], bv_hi = b[o_hi];
    uint32_t* ob = g_h2b + (n * 1024 + y0 * 32) * 32;
#pragma unroll
    for (int nt = 0; nt < 4; nt++) {
#pragma unroll
        for (int c = 0; c < 2; c++) {
            float v0 = fmaxf(acc[nt][c]     + bv_lo, 0.0f);
            float v2 = fmaxf(acc[nt][c + 2] + bv_hi, 0.0f);
            float p0 = __shfl_xor_sync(0xffffffffu, v0, 4);
            float p2 = __shfl_xor_sync(0xffffffffu, v2, 4);
            if (!(g & 1)) {
                int hw = nbase + nt * 8 + tg * 2 + c;
                uint32_t* row = ob + hw * 32;
                row[o_lo >> 1] = pk_bf16(v0, p0);
                row[o_hi >> 1] = pk_bf16(v2, p2);
            }
        }
    }
}

// ---------------- conv3 / deconv1: bf16 mma, m2xn4, 12 weight chunks ----------------
// smem u32: tinb[216 pix][36] (7776) + ws[2][3tap*8kp][72] (2*1728) = 44928 B
template <int SET>
__global__ void __launch_bounds__(256) conv3x3b_k(const float* __restrict__ b) {
    extern __shared__ float dsm[];
    uint32_t* tinb = (uint32_t*)dsm;
    uint32_t* ws   = (uint32_t*)dsm + 7776;
    uint32_t tin_s = (uint32_t)__cvta_generic_to_shared(tinb);
    uint32_t ws_s  = (uint32_t)__cvta_generic_to_shared(ws);
    int n = blockIdx.x >> 3, y0 = (blockIdx.x & 7) * 4;
    int t = threadIdx.x;
    int wid = t >> 5, lane = t & 31;
    int g = lane >> 2, tg = lane & 3;
    int obase0 = (wid & 1) * 32;
    int nbase = (wid >> 1) * 32;
    int o_l0 = obase0 + g,      o_h0 = o_l0 + 8;
    int o_l1 = obase0 + 16 + g, o_h1 = o_l1 + 8;
    const uint32_t* in0 = (SET ? g_zqb : g_h2b) + n * 32768;
    const uint32_t* wsrc = g_wtb + SET * 20736;

    int idx0[4];
#pragma unroll
    for (int nt = 0; nt < 4; nt++) {
        int p = nbase + nt * 8 + g;
        idx0[nt] = (p >> 5) * 36 + (p & 31);
    }

    float acc[2][4][4];
#pragma unroll
    for (int m2 = 0; m2 < 2; m2++)
#pragma unroll
        for (int nt = 0; nt < 4; nt++)
#pragma unroll
            for (int j = 0; j < 4; j++) acc[m2][nt][j] = 0.0f;

    for (int j = t; j < 1632; j += 256) {
        int pix = j >> 3, q = j & 7;
        int r = pix / 34, c = pix - r * 34;
        int iy = y0 - 1 + r, ix = c - 1;
        bool p = ((unsigned)iy < 32u) & ((unsigned)ix < 32u);
        const uint32_t* src = in0 + (p ? (iy * 32 + ix) * 32 : 0) + q * 4;
        cp16z(tin_s + ((r * 36 + c) * 36 + q * 4) * 4, src, p);
    }
    auto load_ws = [&](int buf, int c) {             // chunk = 3 taps (1728 u32)
        const uint32_t* src = wsrc + c * 1728;
        for (int j = t; j < 432; j += 256)
            cp16(ws_s + (buf * 1728 + j * 4) * 4, src + j * 4);
        cp_commit();
    };
    load_ws(0, 0);

    for (int c = 0; c < 12; c++) {
        if (c < 11) { load_ws((c + 1) & 1, c + 1); cp_wait1(); }
        else        { cp_wait0(); }
        __syncthreads();
        const uint32_t* wb = ws + (c & 1) * 1728;
        int sl = c / 3, tapg = c - sl * 3;
        int koff = sl * 8;
#pragma unroll
        for (int tl = 0; tl < 3; tl++) {
            int tt = tapg * 3 + tl;
            int ky = tt / 3, kx = tt - ky * 3;
            const uint32_t* wpb = wb + tl * 576;
            uint32_t a00 = wpb[tg * 72 + o_l0];
            uint32_t a01 = wpb[tg * 72 + o_h0];
            uint32_t a02 = wpb[(tg + 4) * 72 + o_l0];
            uint32_t a03 = wpb[(tg + 4) * 72 + o_h0];
            uint32_t a10 = wpb[tg * 72 + o_l1];
            uint32_t a11 = wpb[tg * 72 + o_h1];
            uint32_t a12 = wpb[(tg + 4) * 72 + o_l1];
            uint32_t a13 = wpb[(tg + 4) * 72 + o_h1];
            int doff = ky * 36 + kx;
#pragma unroll
            for (int nt = 0; nt < 4; nt++) {
                const uint32_t* tp = tinb + (idx0[nt] + doff) * 36 + koff;
                uint32_t rb0 = tp[tg];
                uint32_t rb1 = tp[tg + 4];
                mma_bf16(acc[0][nt][0], acc[0][nt][1], acc[0][nt][2], acc[0][nt][3],
                         a00, a01, a02, a03, rb0, rb1);
                mma_bf16(acc[1][nt][0], acc[1][nt][1], acc[1][nt][2], acc[1][nt][3],
                         a10, a11, a12, a13, rb0, rb1);
            }
        }
        __syncthreads();
    }

    if (SET == 0) {
        float* outbase = g_z + n * 65536 + y0 * 32;
#pragma unroll
        for (int m2 = 0; m2 < 2; m2++) {
            int olo = obase0 + m2 * 16 + g, ohi = olo + 8;
            float bl = b[olo], bh = b[ohi];
#pragma unroll
            for (int nt = 0; nt < 4; nt++) {
                int pc = nbase + nt * 8 + tg * 2;
                *(float2*)(outbase + olo * 1024 + pc) =
                    make_float2(f2tf_f(acc[m2][nt][0] + bl), f2tf_f(acc[m2][nt][1] + bl));
                *(float2*)(outbase + ohi * 1024 + pc) =
                    make_float2(f2tf_f(acc[m2][nt][2] + bh), f2tf_f(acc[m2][nt][3] + bh));
            }
        }
    } else {
        uint32_t* ob = g_d1b + (n * 1024 + y0 * 32) * 32;
#pragma unroll
        for (int m2 = 0; m2 < 2; m2++) {
            int olo = obase0 + m2 * 16 + g, ohi = olo + 8;
            float bl = b[olo], bh = b[ohi];
#pragma unroll
            for (int nt = 0; nt < 4; nt++) {
                float v0 = fmaxf(acc[m2][nt][0] + bl, 0.0f);
                float v1 = fmaxf(acc[m2][nt][1] + bl, 0.0f);
                float v2 = fmaxf(acc[m2][nt][2] + bh, 0.0f);
                float v3 = fmaxf(acc[m2][nt][3] + bh, 0.0f);
                float p0 = __shfl_xor_sync(0xffffffffu, v0, 4);
                float p1 = __shfl_xor_sync(0xffffffffu, v1, 4);
                float p2 = __shfl_xor_sync(0xffffffffu, v2, 4);
                float p3 = __shfl_xor_sync(0xffffffffu, v3, 4);
                if (!(g & 1)) {
                    int pc = nbase + nt * 8 + tg * 2;
                    uint32_t* r0 = ob + pc * 32;
                    uint32_t* r1 = r0 + 32;
                    r0[olo >> 1] = pk_bf16(v0, p0);
                    r1[olo >> 1] = pk_bf16(v1, p1);
                    r0[ohi >> 1] = pk_bf16(v2, p2);
                    r1[ohi >> 1] = pk_bf16(v3, p3);
                }
            }
        }
    }
}

// ---------------- quantize — tf32 mma GEMM + argmin (z pre-rounded tf32) ----------
__global__ void __launch_bounds__(256) quantize_m_k(const float* __restrict__ cb,
                                                    float* out) {
    extern __shared__ float dsm[];
    float* zt   = dsm;
    float* cbt  = dsm + 8704;
    float* minS = dsm + 17408;
    int*   minI = (int*)(dsm + 18432);
    float* cn   = dsm + 19456;
    float* red  = dsm + 19584;
    uint32_t zt_s  = (uint32_t)__cvta_generic_to_shared(zt);
    uint32_t cbt_s = (uint32_t)__cvta_generic_to_shared(cbt);
    int t = threadIdx.x;
    int n = blockIdx.x >> 3, hw0 = (blockIdx.x & 7) * 128;
    int wid = t >> 5, lane = t & 31;
    int g = lane >> 2, tg = lane & 3;
    int mbase = wid * 16;

    const float* zsrc = g_z + n * 65536 + hw0;
    for (int j = t; j < 2048; j += 256) {
        int row = j >> 5, c4 = j & 31;
        cp16(zt_s + (row * 136 + c4 * 4) * 4, zsrc + row * 1024 + c4 * 4);
    }
    for (int j = t; j < 2176; j += 256)
        cp16(cbt_s + j * 16, g_cbt + j * 4);
    cp_commit();
    if (t < 128) {
        float s = 0.0f;
        const float* cp = cb + t * 64;
#pragma unroll
        for (int d = 0; d < 64; d++) s = fmaf(cp[d], cp[d], s);
        cn[t] = s;
    }
    cp_wait0();
    __syncthreads();

    float acc[16][4];
#pragma unroll
    for (int nt = 0; nt < 16; nt++)
#pragma unroll
        for (int j = 0; j < 4; j++) acc[nt][j] = 0.0f;

#pragma unroll
    for (int ks = 0; ks < 8; ks++) {
        const float* a0 = cbt + (ks * 8 + tg) * 136 + mbase + g;
        const float* a1 = cbt + (ks * 8 + tg + 4) * 136 + mbase + g;
        uint32_t ra0 = *(const uint32_t*)a0;
        uint32_t ra1 = *(const uint32_t*)(a0 + 8);
        uint32_t ra2 = *(const uint32_t*)a1;
        uint32_t ra3 = *(const uint32_t*)(a1 + 8);
        const float* b0 = zt + (ks * 8 + tg) * 136 + g;
        const float* b1 = zt + (ks * 8 + tg + 4) * 136 + g;
#pragma unroll
        for (int nt = 0; nt < 16; nt++) {
            uint32_t rb0 = *(const uint32_t*)&b0[nt * 8];
            uint32_t rb1 = *(const uint32_t*)&b1[nt * 8];
            mma_tf32(acc[nt][0], acc[nt][1], acc[nt][2], acc[nt][3],
                     ra0, ra1, ra2, ra3, rb0, rb1);
        }
    }

    float cn_lo = cn[mbase + g], cn_hi = cn[mbase + g + 8];
#pragma unroll
    for (int nt = 0; nt < 16; nt++) {
#pragma unroll
        for (int c2 = 0; c2 < 2; c2++) {
            float s_lo = fmaf(-2.0f, acc[nt][c2],     cn_lo);
            float s_hi = fmaf(-2.0f, acc[nt][c2 + 2], cn_hi);
            float s = s_lo; int idx = mbase + g;
            if (s_hi < s) { s = s_hi; idx = mbase + g + 8; }
#pragma unroll
            for (int m = 4; m <= 16; m <<= 1) {
                float so = __shfl_xor_sync(0xffffffffu, s, m);
                int   io = __shfl_xor_sync(0xffffffffu, idx, m);
                if (so < s || (so == s && io < idx)) { s = so; idx = io; }
            }
            if (g == 0) {
                int px = nt * 8 + tg * 2 + c2;
                minS[wid * 128 + px] = s;
                minI[wid * 128 + px] = idx;
            }
        }
    }
    __syncthreads();

    int px = t & 127, half = t >> 7;
    float bs = minS[px]; int bi = minI[px];
#pragma unroll
    for (int w = 1; w < 8; w++) {
        float s = minS[w * 128 + px]; int i2 = minI[w * 128 + px];
        if (s < bs || (s == bs && i2 < bi)) { bs = s; bi = i2; }
    }
    float vs = 0.0f;
    const float* cbp = cb + bi * 64 + half * 32;
    uint32_t* zq32 = g_zqb + (n * 1024 + hw0 + px) * 32 + half * 16;
#pragma unroll
    for (int d2 = 0; d2 < 16; d2++) {
        float c0 = cbp[2 * d2], c1 = cbp[2 * d2 + 1];
        zq32[d2] = pk_bf16(c0, c1);
        float df0 = zt[(half * 32 + 2 * d2) * 136 + px] - c0;
        float df1 = zt[(half * 32 + 2 * d2 + 1) * 136 + px] - c1;
        vs = fmaf(df0, df0, vs);
        vs = fmaf(df1, df1, vs);
    }
    red[t] = vs;
    __syncthreads();
    for (int s = 128; s > 0; s >>= 1) {
        if (t < s) red[t] += red[t + s];
        __syncthreads();
    }
    if (t == 0) atomicAdd(out + N_XREC + 1, red[0] * (1.0f / (float)N_Z));
}

// ---------------- deconv2: bf16 mma, parity GEMM, 4 ks weight chunks ----------
// smem u32: tinb[4*36 pix][36] (5184) + ws[2][par*tap*kpin][40] (2*5120) = 61696 B
__global__ void __launch_bounds__(256) deconv2b_k(const float* __restrict__ b) {
    extern __shared__ float dsm[];
    uint32_t* tinb = (uint32_t*)dsm;
    uint32_t* ws   = (uint32_t*)dsm + 5184;
    uint32_t tin_s = (uint32_t)__cvta_generic_to_shared(tinb);
    uint32_t ws_s  = (uint32_t)__cvta_generic_to_shared(ws);
    int n = blockIdx.x >> 4, u0 = (blockIdx.x & 15) * 2;
    int t = threadIdx.x;
    int wid = t >> 5, lane = t & 31;
    int g = lane >> 2, tg = lane & 3;
    int half = wid & 1, par = wid >> 1;
    int py = par >> 1, px = par & 1;
    int o_l0 = g, o_h0 = g + 8, o_l1 = g + 16, o_h1 = g + 24;
    const uint32_t* in0 = g_d1b + n * 32768;

    int boff[4];
#pragma unroll
    for (int nt = 0; nt < 4; nt++) {
        int p = half * 32 + nt * 8 + g;
        boff[nt] = (p >> 5) * 36 + (p & 31);
    }

    float acc[2][4][4];
#pragma unroll
    for (int m2 = 0; m2 < 2; m2++)
#pragma unroll
        for (int nt = 0; nt < 4; nt++)
#pragma unroll
            for (int j = 0; j < 4; j++) acc[m2][nt][j] = 0.0f;

    for (int j = t; j < 1088; j += 256) {
        int pix = j >> 3, q = j & 7;
        int r = pix / 34, c = pix - r * 34;
        int yi = u0 - 1 + r, xi = c - 1;
        bool p = ((unsigned)yi < 32u) & ((unsigned)xi < 32u);
        const uint32_t* src = in0 + (p ? (yi * 32 + xi) * 32 : 0) + q * 4;
        cp16z(tin_s + ((r * 36 + c) * 36 + q * 4) * 4, src, p);
    }
    auto load_ws = [&](int buf, int ks) {           // chunk = 5120 u32
        const uint32_t* src = g_wd2b + ks * 5120;
        for (int j = t; j < 1280; j += 256)
            cp16(ws_s + (buf * 5120 + j * 4) * 4, src + j * 4);
        cp_commit();
    };
    load_ws(0, 0);

    for (int ks = 0; ks < 4; ks++) {
        if (ks < 3) { load_ws((ks + 1) & 1, ks + 1); cp_wait1(); }
        else        { cp_wait0(); }
        __syncthreads();
        const uint32_t* wp0 = ws + (ks & 1) * 5120 + par * 1280;  // [tap(4)][kpin(8)][40]
#pragma unroll
        for (int tap = 0; tap < 4; tap++) {
            int jj = tap >> 1, ii = tap & 1;
            int dy = py - jj, dx = px - ii;
            int doff = (1 + dy) * 36 + (1 + dx);
            const uint32_t* wpb = wp0 + tap * 320;
            uint32_t a00 = wpb[tg * 40 + o_l0];
            uint32_t a01 = wpb[tg * 40 + o_h0];
            uint32_t a02 = wpb[(tg + 4) * 40 + o_l0];
            uint32_t a03 = wpb[(tg + 4) * 40 + o_h0];
            uint32_t a10 = wpb[tg * 40 + o_l1];
            uint32_t a11 = wpb[tg * 40 + o_h1];
            uint32_t a12 = wpb[(tg + 4) * 40 + o_l1];
            uint32_t a13 = wpb[(tg + 4) * 40 + o_h1];
#pragma unroll
            for (int nt = 0; nt < 4; nt++) {
                const uint32_t* tp = tinb + (boff[nt] + doff) * 36 + ks * 8;
                uint32_t rb0 = tp[tg];
                uint32_t rb1 = tp[tg + 4];
                mma_bf16(acc[0][nt][0], acc[0][nt][1], acc[0][nt][2], acc[0][nt][3],
                         a00, a01, a02, a03, rb0, rb1);
                mma_bf16(acc[1][nt][0], acc[1][nt][1], acc[1][nt][2], acc[1][nt][3],
                         a10, a11, a12, a13, rb0, rb1);
            }
        }
        __syncthreads();
    }

    float* ob = g_h1 + n * 131072;
#pragma unroll
    for (int m2 = 0; m2 < 2; m2++) {
        int olo = m2 * 16 + g, ohi = olo + 8;
        float bl = b[olo], bh = b[ohi];
#pragma unroll
        for (int nt = 0; nt < 4; nt++) {
#pragma unroll
            for (int c2 = 0; c2 < 2; c2++) {
                int np = half * 32 + nt * 8 + tg * 2 + c2;
                int u_l = np >> 5, v = np & 31;
                int yo = 2 * (u0 + u_l) + py, xo = 2 * v + px;
                ob[olo * 4096 + yo * 64 + xo] = fmaxf(acc[m2][nt][c2]     + bl, 0.0f);
                ob[ohi * 4096 + yo * 64 + xo] = fmaxf(acc[m2][nt][c2 + 2] + bh, 0.0f);
            }
        }
    }
}

// ---------------- deconv3: 32->1, k4 s2 p1, sigmoid + recon loss ----------------
__global__ void __launch_bounds__(256) deconv3t_k(const float* __restrict__ xin,
                                                  const float* __restrict__ w,
                                                  const float* __restrict__ b,
                                                  float* out) {
    __shared__ float tin[2][8][10][66];
    __shared__ float ws3[512];
    __shared__ float red[256];
    uint32_t tin_s = (uint32_t)__cvta_generic_to_shared(&tin[0][0][0][0]);
    int n = blockIdx.x >> 3, y0 = (blockIdx.x & 7) * 16;
    int t = threadIdx.x;
    int ys = t >> 4, x0 = (t & 15) * 8;
    int yo = y0 + ys;
    int ky0 = (yo + 1) & 1;
    int yiA = (yo + 1 - ky0) >> 1;
    int rowA = yiA - (y0 >> 1) + 1;
    int rowB = rowA - 1;
    int cbase = x0 >> 1;

    for (int j = t; j < 512; j += 256) ws3[j] = w[j];

    float acc[8];
#pragma unroll
    for (int s = 0; s < 8; s++) acc[s] = 0.0f;

    const float* in0 = g_h1 + n * 131072;
    auto load_chunk = [&](int buf, int ch) {
        for (int j = t; j < 5280; j += 256) {
            int cc = j / 660, rem = j - cc * 660, r = rem / 66, c = rem - r * 66;
            int yi = (y0 >> 1) - 1 + r, xi = c - 1;
            bool p = ((unsigned)yi < 64u) & ((unsigned)xi < 64u);
            const float* src = in0 + (ch * 8 + cc) * 4096 + (p ? yi * 64 + xi : 0);
            cp4(tin_s + (buf * 5280 + j) * 4, src, p);
        }
        cp_commit();
    };

    load_chunk(0, 0);
    for (int ch = 0; ch < 4; ch++) {
        if (ch < 3) { load_chunk((ch + 1) & 1, ch + 1); cp_wait1(); }
        else        { cp_wait0(); }
        __syncthreads();
        int buf = ch & 1;
#pragma unroll 2
        for (int cc = 0; cc < 8; cc++) {
            float a[6], bb[6];
#pragma unroll
            for (int c = 0; c < 6; c++) {
                a[c]  = tin[buf][cc][rowA][cbase + c];
                bb[c] = tin[buf][cc][rowB][cbase + c];
            }
            int ci = ch * 8 + cc;
            const float* wp = &ws3[ci * 16];
            float wa0 = wp[ky0 * 4 + 0], wa1 = wp[ky0 * 4 + 1];
            float wa2 = wp[ky0 * 4 + 2], wa3 = wp[ky0 * 4 + 3];
            float wb0 = wp[(ky0 + 2) * 4 + 0], wb1 = wp[(ky0 + 2) * 4 + 1];
            float wb2 = wp[(ky0 + 2) * 4 + 2], wb3 = wp[(ky0 + 2) * 4 + 3];
#pragma unroll
            for (int s = 0; s < 8; s++) {
                int ia = (s >> 1) + (s & 1) + 1, ib = ia - 1;
                float v = acc[s];
                if (s & 1) {
                    v = fmaf(a[ia],  wa0, v);
                    v = fmaf(a[ib],  wa2, v);
                    v = fmaf(bb[ia], wb0, v);
                    v = fmaf(bb[ib], wb2, v);
                } else {
                    v = fmaf(a[ia],  wa1, v);
                    v = fmaf(a[ib],  wa3, v);
                    v = fmaf(bb[ia], wb1, v);
                    v = fmaf(bb[ib], wb3, v);
                }
                acc[s] = v;
            }
        }
        __syncthreads();
    }

    float b0 = b[0];
    const float* xp = xin + n * 16384 + yo * 128 + x0;
    float* op = out + n * 16384 + yo * 128 + x0;
    float ls = 0.0f;
    float rv[8];
#pragma unroll
    for (int s = 0; s < 8; s++) {
        float r = 1.0f / (1.0f + expf(-(acc[s] + b0)));
        rv[s] = r;
        float df = r - xp[s];
        ls = fmaf(df, df, ls);
    }
    *(float4*)(op)     = make_float4(rv[0], rv[1], rv[2], rv[3]);
    *(float4*)(op + 4) = make_float4(rv[4], rv[5], rv[6], rv[7]);

    red[t] = ls;
    __syncthreads();
    for (int s = 128; s > 0; s >>= 1) {
        if (t < s) red[t] += red[t + s];
        __syncthreads();
    }
    if (t == 0) atomicAdd(out + N_XREC, red[0] * (1.0f / (float)N_XREC));
}

// ---------------- launch ----------------
extern "C" void kernel_launch(void* const* d_in, const int* in_sizes, int n_in,
                              void* d_out, int out_size) {
    const float* x   = (const float*)d_in[0];
    const float* w1  = (const float*)d_in[1];
    const float* b1  = (const float*)d_in[2];
    const float* w2  = (const float*)d_in[3];
    const float* b2  = (const float*)d_in[4];
    const float* w3  = (const float*)d_in[5];
    const float* b3  = (const float*)d_in[6];
    const float* cb  = (const float*)d_in[7];
    const float* dw1 = (const float*)d_in[8];
    const float* db1 = (const float*)d_in[9];
    const float* dw2 = (const float*)d_in[10];
    const float* db2 = (const float*)d_in[11];
    const float* dw3 = (const float*)d_in[12];
    const float* db3 = (const float*)d_in[13];
    float* out = (float*)d_out;

    static bool attr_done = false;
    if (!attr_done) {
        cudaFuncSetAttribute(conv2b_k, cudaFuncAttributeMaxDynamicSharedMemorySize, 46944);
        cudaFuncSetAttribute(conv3x3b_k<0>, cudaFuncAttributeMaxDynamicSharedMemorySize, 44928);
        cudaFuncSetAttribute(conv3x3b_k<1>, cudaFuncAttributeMaxDynamicSharedMemorySize, 44928);
        cudaFuncSetAttribute(deconv2b_k, cudaFuncAttributeMaxDynamicSharedMemorySize, 61696);
        cudaFuncSetAttribute(quantize_m_k, cudaFuncAttributeMaxDynamicSharedMemorySize, 79360);
        attr_done = true;
    }

    prep_all_k <<<348,  256>>>(w3, dw1, w2, dw2, cb, out);
    conv1_k    <<<2048, 256>>>(x, w1, b1);
    conv2b_k   <<<2048, 256, 46944>>>(b2);
    conv3x3b_k<0><<<1024, 256, 44928>>>(b3);
    quantize_m_k<<<1024, 256, 79360>>>(cb, out);
    conv3x3b_k<1><<<1024, 256, 44928>>>(db1);
    deconv2b_k <<<2048, 256, 61696>>>(db2);
    deconv3t_k <<<1024, 256>>>(x, dw3, db3, out);
}

// round 16
// speedup vs baseline: 1.0152x; 1.0152x over previous
#include <cuda_runtime.h>
#include <stdint.h>
#include <math.h>

// ---------------- geometry ----------------
// x      : [128,  1, 128, 128]
// h1b    : [128, 4096hw, 32ci]   conv1 + relu -> bf16         (g_h1b)
// h2b    : [128, 1024hw, 64ci]   conv2 (bf16 mma) -> bf16     (g_h2b)
// z      : [128, 64,  32,  32]   conv3 (bf16 mma) [tf32]      (g_z)
// zqb    : [128, 1024hw, 64ci]   codebook gather -> bf16      (g_zqb)
// d1b    : [128, 1024hw, 64ci]   deconv1 (bf16 mma) -> bf16   (g_d1b)
// d2     : [128, 32,  64,  64]   deconv2 (bf16 mma) fp32      (g_h1)
// x_rec  : [128,  1, 128, 128]   -> d_out[0 : 2097152]
// d_out[2097152] = recon_loss, d_out[2097153] = vq_loss

#define N_XREC   2097152
#define N_Z      8388608

__device__ float    g_h1[128 * 32 * 64 * 64];
__device__ float    g_z [128 * 64 * 32 * 32];
__device__ uint32_t g_h1b[128 * 4096 * 16];
__device__ uint32_t g_h2b[128 * 1024 * 32];
__device__ uint32_t g_zqb[128 * 1024 * 32];
__device__ uint32_t g_d1b[128 * 1024 * 32];
// bf16x2 3x3 weights: [set][sl(4)][tap(9)][kp(8)][72]
__device__ uint32_t g_wtb[2 * 20736];
// bf16x2 conv2 weights: [tap(16)][kp(16)][72]
__device__ uint32_t g_w2b[18432];
// bf16x2 deconv2 weights: [par(4)][tap(4)][kp(32)][40]
__device__ uint32_t g_wd2b[20480];
// tf32-rounded codebook: [k(64)][136]
__device__ float g_cbt[8704];

// ---------------- cp.async helpers ----------------
__device__ __forceinline__ void cp4(uint32_t dst, const float* src, bool p) {
    asm volatile("cp.async.ca.shared.global [%0], [%1], 4, %2;"
                 :: "r"(dst), "l"(src), "r"(p ? 4u : 0u));
}
__device__ __forceinline__ void cp8z(uint32_t dst, const void* src, bool p) {
    asm volatile("cp.async.ca.shared.global [%0], [%1], 8, %2;"
                 :: "r"(dst), "l"(src), "r"(p ? 8u : 0u));
}
__device__ __forceinline__ void cp16(uint32_t dst, const void* src) {
    asm volatile("cp.async.ca.shared.global [%0], [%1], 16;"
                 :: "r"(dst), "l"(src));
}
__device__ __forceinline__ void cp16z(uint32_t dst, const void* src, bool p) {
    asm volatile("cp.async.ca.shared.global [%0], [%1], 16, %2;"
                 :: "r"(dst), "l"(src), "r"(p ? 16u : 0u));
}
__device__ __forceinline__ void cp_commit() {
    asm volatile("cp.async.commit_group;");
}
__device__ __forceinline__ void cp_wait1() {
    asm volatile("cp.async.wait_group 1;");
}
__device__ __forceinline__ void cp_wait0() {
    asm volatile("cp.async.wait_group 0;");
}

// ---------------- mma helpers ----------------
__device__ __forceinline__ uint32_t f2tf(float f) {
    uint32_t r; asm("cvt.rna.tf32.f32 %0, %1;" : "=r"(r) : "f"(f)); return r;
}
__device__ __forceinline__ float f2tf_f(float f) {
    uint32_t r = f2tf(f); return __uint_as_float(r);
}
__device__ __forceinline__ uint32_t pk_bf16(float lo, float hi) {
    uint32_t r; asm("cvt.rn.bf16x2.f32 %0, %1, %2;" : "=r"(r) : "f"(hi), "f"(lo));
    return r;
}
__device__ __forceinline__ void mma_tf32(float& d0, float& d1, float& d2, float& d3,
                                         uint32_t a0, uint32_t a1, uint32_t a2, uint32_t a3,
                                         uint32_t b0, uint32_t b1) {
    asm volatile("mma.sync.aligned.m16n8k8.row.col.f32.tf32.tf32.f32 "
                 "{%0,%1,%2,%3}, {%4,%5,%6,%7}, {%8,%9}, {%0,%1,%2,%3};"
                 : "+f"(d0), "+f"(d1), "+f"(d2), "+f"(d3)
                 : "r"(a0), "r"(a1), "r"(a2), "r"(a3), "r"(b0), "r"(b1));
}
__device__ __forceinline__ void mma_bf16(float& d0, float& d1, float& d2, float& d3,
                                         uint32_t a0, uint32_t a1, uint32_t a2, uint32_t a3,
                                         uint32_t b0, uint32_t b1) {
    asm volatile("mma.sync.aligned.m16n8k16.row.col.f32.bf16.bf16.f32 "
                 "{%0,%1,%2,%3}, {%4,%5,%6,%7}, {%8,%9}, {%0,%1,%2,%3};"
                 : "+f"(d0), "+f"(d1), "+f"(d2), "+f"(d3)
                 : "r"(a0), "r"(a1), "r"(a2), "r"(a3), "r"(b0), "r"(b1));
}

// ---------------- merged prep ----------------
__global__ void __launch_bounds__(256) prep_all_k(const float* __restrict__ w3,
                                                  const float* __restrict__ dw1,
                                                  const float* __restrict__ w2,
                                                  const float* __restrict__ dw2,
                                                  const float* __restrict__ cb,
                                                  float* out) {
    int i = blockIdx.x * 256 + threadIdx.x;
    if (i < 2) { out[N_XREC + i] = 0.0f; }
    if (i < 41472) {
        int set = i / 20736, r = i - set * 20736;
        int o = r % 72, q = r / 72;
        int kp = q & 7, q2 = q >> 3;
        int tap = q2 % 9, sl = q2 / 9;
        int ci0 = sl * 16 + 2 * kp;
        float v0 = 0.0f, v1 = 0.0f;
        if (o < 64) {
            if (set) {
                v0 = dw1[(ci0 * 64 + o) * 9 + (8 - tap)];
                v1 = dw1[((ci0 + 1) * 64 + o) * 9 + (8 - tap)];
            } else {
                v0 = w3[(o * 64 + ci0) * 9 + tap];
                v1 = w3[(o * 64 + ci0 + 1) * 9 + tap];
            }
        }
        g_wtb[i] = pk_bf16(v0, v1);
    } else if (i < 59904) {
        int j = i - 41472;
        int o = j % 72, q = j / 72;
        int kp = q & 15, tap = q >> 4;
        int ci0 = 2 * kp;
        float v0 = 0.0f, v1 = 0.0f;
        if (o < 64) {
            v0 = w2[(o * 32 + ci0) * 16 + tap];
            v1 = w2[(o * 32 + ci0 + 1) * 16 + tap];
        }
        g_w2b[j] = pk_bf16(v0, v1);
    } else if (i < 80384) {
        int j = i - 59904;
        int o = j % 40, q = j / 40;
        int kp = q & 31, q2 = q >> 5;
        int tap = q2 & 3, par = q2 >> 2;
        int py = par >> 1, px = par & 1;
        int ky = (1 - py) + 2 * (tap >> 1);
        int kx = (1 - px) + 2 * (tap & 1);
        int ci0 = 2 * kp;
        float v0 = 0.0f, v1 = 0.0f;
        if (o < 32) {
            v0 = dw2[(ci0 * 32 + o) * 16 + ky * 4 + kx];
            v1 = dw2[((ci0 + 1) * 32 + o) * 16 + ky * 4 + kx];
        }
        g_wd2b[j] = pk_bf16(v0, v1);
    } else if (i < 89088) {
        int j = i - 80384;
        int m = j % 136, k = j / 136;
        float v = 0.0f;
        if (m < 128) v = cb[m * 64 + k];
        g_cbt[j] = f2tf_f(v);
    }
}

// ---------------- conv1: 1->32, k4 s2 p1, relu; output bf16 [hw][ci] ----------------
__global__ void __launch_bounds__(256) conv1_k(const float* __restrict__ x,
                                               const float* __restrict__ w,
                                               const float* __restrict__ b) {
    __shared__ float tin[10][132];
    __shared__ float ws[512];
    __shared__ float bs[32];
    int n = blockIdx.x >> 4, y0 = (blockIdx.x & 15) * 4;
    int t = threadIdx.x;
    int xo = t & 63, ys = t >> 6, yo = y0 + ys;
    for (int i = t; i < 512; i += 256) ws[i] = w[i];
    if (t < 32) bs[t] = b[t];
    const float* xp = x + n * 16384;
    for (int j = t; j < 1320; j += 256) {
        int r = j / 132, c = j - r * 132;
        int iy = 2 * y0 - 1 + r, ix = c - 1;
        float v = 0.0f;
        if ((unsigned)iy < 128u && (unsigned)ix < 128u) v = xp[iy * 128 + ix];
        tin[r][c] = v;
    }
    __syncthreads();

    float xin[16];
#pragma unroll
    for (int ky = 0; ky < 4; ky++)
#pragma unroll
        for (int kx = 0; kx < 4; kx++)
            xin[ky * 4 + kx] = tin[2 * ys + ky][2 * xo + kx];

    float acc[32];
#pragma unroll 4
    for (int o = 0; o < 32; o++) {
        float a = bs[o];
#pragma unroll
        for (int k = 0; k < 16; k++) a = fmaf(xin[k], ws[o * 16 + k], a);
        acc[o] = fmaxf(a, 0.0f);
    }
    uint32_t pk[16];
#pragma unroll
    for (int j = 0; j < 16; j++) pk[j] = pk_bf16(acc[2 * j], acc[2 * j + 1]);
    uint4* op = (uint4*)(g_h1b + (n * 4096 + yo * 64 + xo) * 16);
#pragma unroll
    for (int q = 0; q < 4; q++)
        op[q] = make_uint4(pk[4 * q], pk[4 * q + 1], pk[4 * q + 2], pk[4 * q + 3]);
}

// ---------------- conv2: 32->64, k4 s2 p1, relu — bf16 mma, LDG weights ----------
// smem u32: tinb[6*66 pix][18] = 7128 (28512 B). Zero mainloop barriers.
__global__ void __launch_bounds__(256) conv2b_k(const float* __restrict__ b) {
    extern __shared__ float dsm[];
    uint32_t* tinb = (uint32_t*)dsm;
    uint32_t tin_s = (uint32_t)__cvta_generic_to_shared(tinb);
    int n = blockIdx.x >> 4, y0 = (blockIdx.x & 15) * 2;
    int t = threadIdx.x;
    int wid = t >> 5, lane = t & 31;
    int g = lane >> 2, tg = lane & 3;
    int obase = (wid & 3) * 16;
    int nbase = (wid >> 2) * 32;
    int o_lo = obase + g, o_hi = o_lo + 8;
    const uint32_t* in0 = g_h1b + n * 65536;

    int boff[4];
#pragma unroll
    for (int nt = 0; nt < 4; nt++) {
        int p = nbase + nt * 8 + g;
        boff[nt] = (p >> 5) * 132 + (p & 31) * 2;
    }

    float acc[4][4];
#pragma unroll
    for (int nt = 0; nt < 4; nt++)
#pragma unroll
        for (int j = 0; j < 4; j++) acc[nt][j] = 0.0f;

    for (int j = t; j < 3168; j += 256) {
        int pix = j >> 3, q = j & 7;
        int r = pix / 66, c = pix - r * 66;
        int iy = 2 * y0 - 1 + r, ix = c - 1;
        bool p = ((unsigned)iy < 64u) & ((unsigned)ix < 64u);
        const uint32_t* src = in0 + (p ? (iy * 64 + ix) * 16 : 0) + q * 2;
        cp8z(tin_s + ((r * 66 + c) * 18 + q * 2) * 4, src, p);
    }
    cp_commit();
    cp_wait0();
    __syncthreads();

#pragma unroll
    for (int tap = 0; tap < 16; tap++) {
        int ky = tap >> 2, kx = tap & 3;
        int doff = ky * 66 + kx;
#pragma unroll
        for (int ks = 0; ks < 2; ks++) {
            const uint32_t* wpb = g_w2b + (tap * 16 + ks * 8) * 72;
            uint32_t ra0 = __ldg(&wpb[tg * 72 + o_lo]);
            uint32_t ra1 = __ldg(&wpb[tg * 72 + o_hi]);
            uint32_t ra2 = __ldg(&wpb[(tg + 4) * 72 + o_lo]);
            uint32_t ra3 = __ldg(&wpb[(tg + 4) * 72 + o_hi]);
#pragma unroll
            for (int nt = 0; nt < 4; nt++) {
                const uint32_t* tp = tinb + (boff[nt] + doff) * 18 + ks * 8;
                uint32_t rb0 = tp[tg];
                uint32_t rb1 = tp[tg + 4];
                mma_bf16(acc[nt][0], acc[nt][1], acc[nt][2], acc[nt][3],
                         ra0, ra1, ra2, ra3, rb0, rb1);
            }
        }
    }

    float bv_lo = b[o_lo], bv_hi = b[o_hi];
    uint32_t* ob = g_h2b + (n * 1024 + y0 * 32) * 32;
#pragma unroll
    for (int nt = 0; nt < 4; nt++) {
#pragma unroll
        for (int c = 0; c < 2; c++) {
            float v0 = fmaxf(acc[nt][c]     + bv_lo, 0.0f);
            float v2 = fmaxf(acc[nt][c + 2] + bv_hi, 0.0f);
            float p0 = __shfl_xor_sync(0xffffffffu, v0, 4);
            float p2 = __shfl_xor_sync(0xffffffffu, v2, 4);
            if (!(g & 1)) {
                int hw = nbase + nt * 8 + tg * 2 + c;
                uint32_t* row = ob + hw * 32;
                row[o_lo >> 1] = pk_bf16(v0, p0);
                row[o_hi >> 1] = pk_bf16(v2, p2);
            }
        }
    }
}

// ---------------- conv3 / deconv1: bf16 mma m2xn4, LDG weights ----------------
// smem u32: tinb[216 pix][36] = 7776 (31104 B). Zero mainloop barriers.
template <int SET>
__global__ void __launch_bounds__(256) conv3x3b_k(const float* __restrict__ b) {
    extern __shared__ float dsm[];
    uint32_t* tinb = (uint32_t*)dsm;
    uint32_t tin_s = (uint32_t)__cvta_generic_to_shared(tinb);
    int n = blockIdx.x >> 3, y0 = (blockIdx.x & 7) * 4;
    int t = threadIdx.x;
    int wid = t >> 5, lane = t & 31;
    int g = lane >> 2, tg = lane & 3;
    int obase0 = (wid & 1) * 32;
    int nbase = (wid >> 1) * 32;
    int o_l0 = obase0 + g,      o_h0 = o_l0 + 8;
    int o_l1 = obase0 + 16 + g, o_h1 = o_l1 + 8;
    const uint32_t* in0 = (SET ? g_zqb : g_h2b) + n * 32768;
    const uint32_t* wsrc = g_wtb + SET * 20736;

    int idx0[4];
#pragma unroll
    for (int nt = 0; nt < 4; nt++) {
        int p = nbase + nt * 8 + g;
        idx0[nt] = (p >> 5) * 36 + (p & 31);
    }

    float acc[2][4][4];
#pragma unroll
    for (int m2 = 0; m2 < 2; m2++)
#pragma unroll
        for (int nt = 0; nt < 4; nt++)
#pragma unroll
            for (int j = 0; j < 4; j++) acc[m2][nt][j] = 0.0f;

    for (int j = t; j < 1632; j += 256) {
        int pix = j >> 3, q = j & 7;
        int r = pix / 34, c = pix - r * 34;
        int iy = y0 - 1 + r, ix = c - 1;
        bool p = ((unsigned)iy < 32u) & ((unsigned)ix < 32u);
        const uint32_t* src = in0 + (p ? (iy * 32 + ix) * 32 : 0) + q * 4;
        cp16z(tin_s + ((r * 36 + c) * 36 + q * 4) * 4, src, p);
    }
    cp_commit();
    cp_wait0();
    __syncthreads();

    for (int sl = 0; sl < 4; sl++) {
        int koff = sl * 8;
#pragma unroll
        for (int tap = 0; tap < 9; tap++) {
            int ky = tap / 3, kx = tap - ky * 3;
            const uint32_t* wpb = wsrc + (sl * 9 + tap) * 576;
            uint32_t a00 = __ldg(&wpb[tg * 72 + o_l0]);
            uint32_t a01 = __ldg(&wpb[tg * 72 + o_h0]);
            uint32_t a02 = __ldg(&wpb[(tg + 4) * 72 + o_l0]);
            uint32_t a03 = __ldg(&wpb[(tg + 4) * 72 + o_h0]);
            uint32_t a10 = __ldg(&wpb[tg * 72 + o_l1]);
            uint32_t a11 = __ldg(&wpb[tg * 72 + o_h1]);
            uint32_t a12 = __ldg(&wpb[(tg + 4) * 72 + o_l1]);
            uint32_t a13 = __ldg(&wpb[(tg + 4) * 72 + o_h1]);
            int doff = ky * 36 + kx;
#pragma unroll
            for (int nt = 0; nt < 4; nt++) {
                const uint32_t* tp = tinb + (idx0[nt] + doff) * 36 + koff;
                uint32_t rb0 = tp[tg];
                uint32_t rb1 = tp[tg + 4];
                mma_bf16(acc[0][nt][0], acc[0][nt][1], acc[0][nt][2], acc[0][nt][3],
                         a00, a01, a02, a03, rb0, rb1);
                mma_bf16(acc[1][nt][0], acc[1][nt][1], acc[1][nt][2], acc[1][nt][3],
                         a10, a11, a12, a13, rb0, rb1);
            }
        }
    }

    if (SET == 0) {
        float* outbase = g_z + n * 65536 + y0 * 32;
#pragma unroll
        for (int m2 = 0; m2 < 2; m2++) {
            int olo = obase0 + m2 * 16 + g, ohi = olo + 8;
            float bl = b[olo], bh = b[ohi];
#pragma unroll
            for (int nt = 0; nt < 4; nt++) {
                int pc = nbase + nt * 8 + tg * 2;
                *(float2*)(outbase + olo * 1024 + pc) =
                    make_float2(f2tf_f(acc[m2][nt][0] + bl), f2tf_f(acc[m2][nt][1] + bl));
                *(float2*)(outbase + ohi * 1024 + pc) =
                    make_float2(f2tf_f(acc[m2][nt][2] + bh), f2tf_f(acc[m2][nt][3] + bh));
            }
        }
    } else {
        uint32_t* ob = g_d1b + (n * 1024 + y0 * 32) * 32;
#pragma unroll
        for (int m2 = 0; m2 < 2; m2++) {
            int olo = obase0 + m2 * 16 + g, ohi = olo + 8;
            float bl = b[olo], bh = b[ohi];
#pragma unroll
            for (int nt = 0; nt < 4; nt++) {
                float v0 = fmaxf(acc[m2][nt][0] + bl, 0.0f);
                float v1 = fmaxf(acc[m2][nt][1] + bl, 0.0f);
                float v2 = fmaxf(acc[m2][nt][2] + bh, 0.0f);
                float v3 = fmaxf(acc[m2][nt][3] + bh, 0.0f);
                float p0 = __shfl_xor_sync(0xffffffffu, v0, 4);
                float p1 = __shfl_xor_sync(0xffffffffu, v1, 4);
                float p2 = __shfl_xor_sync(0xffffffffu, v2, 4);
                float p3 = __shfl_xor_sync(0xffffffffu, v3, 4);
                if (!(g & 1)) {
                    int pc = nbase + nt * 8 + tg * 2;
                    uint32_t* r0 = ob + pc * 32;
                    uint32_t* r1 = r0 + 32;
                    r0[olo >> 1] = pk_bf16(v0, p0);
                    r1[olo >> 1] = pk_bf16(v1, p1);
                    r0[ohi >> 1] = pk_bf16(v2, p2);
                    r1[ohi >> 1] = pk_bf16(v3, p3);
                }
            }
        }
    }
}

// ---------------- quantize — tf32 mma GEMM + argmin (z pre-rounded tf32) ----------
__global__ void __launch_bounds__(256) quantize_m_k(const float* __restrict__ cb,
                                                    float* out) {
    extern __shared__ float dsm[];
    float* zt   = dsm;
    float* cbt  = dsm + 8704;
    float* minS = dsm + 17408;
    int*   minI = (int*)(dsm + 18432);
    float* cn   = dsm + 19456;
    float* red  = dsm + 19584;
    uint32_t zt_s  = (uint32_t)__cvta_generic_to_shared(zt);
    uint32_t cbt_s = (uint32_t)__cvta_generic_to_shared(cbt);
    int t = threadIdx.x;
    int n = blockIdx.x >> 3, hw0 = (blockIdx.x & 7) * 128;
    int wid = t >> 5, lane = t & 31;
    int g = lane >> 2, tg = lane & 3;
    int mbase = wid * 16;

    const float* zsrc = g_z + n * 65536 + hw0;
    for (int j = t; j < 2048; j += 256) {
        int row = j >> 5, c4 = j & 31;
        cp16(zt_s + (row * 136 + c4 * 4) * 4, zsrc + row * 1024 + c4 * 4);
    }
    for (int j = t; j < 2176; j += 256)
        cp16(cbt_s + j * 16, g_cbt + j * 4);
    cp_commit();
    if (t < 128) {
        float s = 0.0f;
        const float* cp = cb + t * 64;
#pragma unroll
        for (int d = 0; d < 64; d++) s = fmaf(cp[d], cp[d], s);
        cn[t] = s;
    }
    cp_wait0();
    __syncthreads();

    float acc[16][4];
#pragma unroll
    for (int nt = 0; nt < 16; nt++)
#pragma unroll
        for (int j = 0; j < 4; j++) acc[nt][j] = 0.0f;

#pragma unroll
    for (int ks = 0; ks < 8; ks++) {
        const float* a0 = cbt + (ks * 8 + tg) * 136 + mbase + g;
        const float* a1 = cbt + (ks * 8 + tg + 4) * 136 + mbase + g;
        uint32_t ra0 = *(const uint32_t*)a0;
        uint32_t ra1 = *(const uint32_t*)(a0 + 8);
        uint32_t ra2 = *(const uint32_t*)a1;
        uint32_t ra3 = *(const uint32_t*)(a1 + 8);
        const float* b0 = zt + (ks * 8 + tg) * 136 + g;
        const float* b1 = zt + (ks * 8 + tg + 4) * 136 + g;
#pragma unroll
        for (int nt = 0; nt < 16; nt++) {
            uint32_t rb0 = *(const uint32_t*)&b0[nt * 8];
            uint32_t rb1 = *(const uint32_t*)&b1[nt * 8];
            mma_tf32(acc[nt][0], acc[nt][1], acc[nt][2], acc[nt][3],
                     ra0, ra1, ra2, ra3, rb0, rb1);
        }
    }

    float cn_lo = cn[mbase + g], cn_hi = cn[mbase + g + 8];
#pragma unroll
    for (int nt = 0; nt < 16; nt++) {
#pragma unroll
        for (int c2 = 0; c2 < 2; c2++) {
            float s_lo = fmaf(-2.0f, acc[nt][c2],     cn_lo);
            float s_hi = fmaf(-2.0f, acc[nt][c2 + 2], cn_hi);
            float s = s_lo; int idx = mbase + g;
            if (s_hi < s) { s = s_hi; idx = mbase + g + 8; }
#pragma unroll
            for (int m = 4; m <= 16; m <<= 1) {
                float so = __shfl_xor_sync(0xffffffffu, s, m);
                int   io = __shfl_xor_sync(0xffffffffu, idx, m);
                if (so < s || (so == s && io < idx)) { s = so; idx = io; }
            }
            if (g == 0) {
                int px = nt * 8 + tg * 2 + c2;
                minS[wid * 128 + px] = s;
                minI[wid * 128 + px] = idx;
            }
        }
    }
    __syncthreads();

    int px = t & 127, half = t >> 7;
    float bs = minS[px]; int bi = minI[px];
#pragma unroll
    for (int w = 1; w < 8; w++) {
        float s = minS[w * 128 + px]; int i2 = minI[w * 128 + px];
        if (s < bs || (s == bs && i2 < bi)) { bs = s; bi = i2; }
    }
    float vs = 0.0f;
    const float* cbp = cb + bi * 64 + half * 32;
    uint32_t* zq32 = g_zqb + (n * 1024 + hw0 + px) * 32 + half * 16;
#pragma unroll
    for (int d2 = 0; d2 < 16; d2++) {
        float c0 = cbp[2 * d2], c1 = cbp[2 * d2 + 1];
        zq32[d2] = pk_bf16(c0, c1);
        float df0 = zt[(half * 32 + 2 * d2) * 136 + px] - c0;
        float df1 = zt[(half * 32 + 2 * d2 + 1) * 136 + px] - c1;
        vs = fmaf(df0, df0, vs);
        vs = fmaf(df1, df1, vs);
    }
    red[t] = vs;
    __syncthreads();
    for (int s = 128; s > 0; s >>= 1) {
        if (t < s) red[t] += red[t + s];
        __syncthreads();
    }
    if (t == 0) atomicAdd(out + N_XREC + 1, red[0] * (1.0f / (float)N_Z));
}

// ---------------- deconv2: bf16 mma parity GEMM, LDG weights ----------
// smem u32: tinb[4*36 pix][36] = 5184 (20736 B). Zero mainloop barriers.
__global__ void __launch_bounds__(256) deconv2b_k(const float* __restrict__ b) {
    extern __shared__ float dsm[];
    uint32_t* tinb = (uint32_t*)dsm;
    uint32_t tin_s = (uint32_t)__cvta_generic_to_shared(tinb);
    int n = blockIdx.x >> 4, u0 = (blockIdx.x & 15) * 2;
    int t = threadIdx.x;
    int wid = t >> 5, lane = t & 31;
    int g = lane >> 2, tg = lane & 3;
    int half = wid & 1, par = wid >> 1;
    int py = par >> 1, px = par & 1;
    int o_l0 = g, o_h0 = g + 8, o_l1 = g + 16, o_h1 = g + 24;
    const uint32_t* in0 = g_d1b + n * 32768;

    int boff[4];
#pragma unroll
    for (int nt = 0; nt < 4; nt++) {
        int p = half * 32 + nt * 8 + g;
        boff[nt] = (p >> 5) * 36 + (p & 31);
    }

    float acc[2][4][4];
#pragma unroll
    for (int m2 = 0; m2 < 2; m2++)
#pragma unroll
        for (int nt = 0; nt < 4; nt++)
#pragma unroll
            for (int j = 0; j < 4; j++) acc[m2][nt][j] = 0.0f;

    for (int j = t; j < 1088; j += 256) {
        int pix = j >> 3, q = j & 7;
        int r = pix / 34, c = pix - r * 34;
        int yi = u0 - 1 + r, xi = c - 1;
        bool p = ((unsigned)yi < 32u) & ((unsigned)xi < 32u);
        const uint32_t* src = in0 + (p ? (yi * 32 + xi) * 32 : 0) + q * 4;
        cp16z(tin_s + ((r * 36 + c) * 36 + q * 4) * 4, src, p);
    }
    cp_commit();
    cp_wait0();
    __syncthreads();

    const uint32_t* wp0 = g_wd2b + par * 5120;     // [tap(4)][kp(32)][40]
#pragma unroll
    for (int tap = 0; tap < 4; tap++) {
        int jj = tap >> 1, ii = tap & 1;
        int dy = py - jj, dx = px - ii;
        int doff = (1 + dy) * 36 + (1 + dx);
        const uint32_t* wpt = wp0 + tap * 1280;
#pragma unroll
        for (int ks = 0; ks < 4; ks++) {
            const uint32_t* wpb = wpt + ks * 8 * 40;
            uint32_t a00 = __ldg(&wpb[tg * 40 + o_l0]);
            uint32_t a01 = __ldg(&wpb[tg * 40 + o_h0]);
            uint32_t a02 = __ldg(&wpb[(tg + 4) * 40 + o_l0]);
            uint32_t a03 = __ldg(&wpb[(tg + 4) * 40 + o_h0]);
            uint32_t a10 = __ldg(&wpb[tg * 40 + o_l1]);
            uint32_t a11 = __ldg(&wpb[tg * 40 + o_h1]);
            uint32_t a12 = __ldg(&wpb[(tg + 4) * 40 + o_l1]);
            uint32_t a13 = __ldg(&wpb[(tg + 4) * 40 + o_h1]);
#pragma unroll
            for (int nt = 0; nt < 4; nt++) {
                const uint32_t* tp = tinb + (boff[nt] + doff) * 36 + ks * 8;
                uint32_t rb0 = tp[tg];
                uint32_t rb1 = tp[tg + 4];
                mma_bf16(acc[0][nt][0], acc[0][nt][1], acc[0][nt][2], acc[0][nt][3],
                         a00, a01, a02, a03, rb0, rb1);
                mma_bf16(acc[1][nt][0], acc[1][nt][1], acc[1][nt][2], acc[1][nt][3],
                         a10, a11, a12, a13, rb0, rb1);
            }
        }
    }

    float* ob = g_h1 + n * 131072;
#pragma unroll
    for (int m2 = 0; m2 < 2; m2++) {
        int olo = m2 * 16 + g, ohi = olo + 8;
        float bl = b[olo], bh = b[ohi];
#pragma unroll
        for (int nt = 0; nt < 4; nt++) {
#pragma unroll
            for (int c2 = 0; c2 < 2; c2++) {
                int np = half * 32 + nt * 8 + tg * 2 + c2;
                int u_l = np >> 5, v = np & 31;
                int yo = 2 * (u0 + u_l) + py, xo = 2 * v + px;
                ob[olo * 4096 + yo * 64 + xo] = fmaxf(acc[m2][nt][c2]     + bl, 0.0f);
                ob[ohi * 4096 + yo * 64 + xo] = fmaxf(acc[m2][nt][c2 + 2] + bh, 0.0f);
            }
        }
    }
}

// ---------------- deconv3: 32->1, k4 s2 p1, sigmoid + recon loss ----------------
__global__ void __launch_bounds__(256) deconv3t_k(const float* __restrict__ xin,
                                                  const float* __restrict__ w,
                                                  const float* __restrict__ b,
                                                  float* out) {
    __shared__ float tin[2][8][10][66];
    __shared__ float ws3[512];
    __shared__ float red[256];
    uint32_t tin_s = (uint32_t)__cvta_generic_to_shared(&tin[0][0][0][0]);
    int n = blockIdx.x >> 3, y0 = (blockIdx.x & 7) * 16;
    int t = threadIdx.x;
    int ys = t >> 4, x0 = (t & 15) * 8;
    int yo = y0 + ys;
    int ky0 = (yo + 1) & 1;
    int yiA = (yo + 1 - ky0) >> 1;
    int rowA = yiA - (y0 >> 1) + 1;
    int rowB = rowA - 1;
    int cbase = x0 >> 1;

    for (int j = t; j < 512; j += 256) ws3[j] = w[j];

    float acc[8];
#pragma unroll
    for (int s = 0; s < 8; s++) acc[s] = 0.0f;

    const float* in0 = g_h1 + n * 131072;
    auto load_chunk = [&](int buf, int ch) {
        for (int j = t; j < 5280; j += 256) {
            int cc = j / 660, rem = j - cc * 660, r = rem / 66, c = rem - r * 66;
            int yi = (y0 >> 1) - 1 + r, xi = c - 1;
            bool p = ((unsigned)yi < 64u) & ((unsigned)xi < 64u);
            const float* src = in0 + (ch * 8 + cc) * 4096 + (p ? yi * 64 + xi : 0);
            cp4(tin_s + (buf * 5280 + j) * 4, src, p);
        }
        cp_commit();
    };

    load_chunk(0, 0);
    for (int ch = 0; ch < 4; ch++) {
        if (ch < 3) { load_chunk((ch + 1) & 1, ch + 1); cp_wait1(); }
        else        { cp_wait0(); }
        __syncthreads();
        int buf = ch & 1;
#pragma unroll 2
        for (int cc = 0; cc < 8; cc++) {
            float a[6], bb[6];
#pragma unroll
            for (int c = 0; c < 6; c++) {
                a[c]  = tin[buf][cc][rowA][cbase + c];
                bb[c] = tin[buf][cc][rowB][cbase + c];
            }
            int ci = ch * 8 + cc;
            const float* wp = &ws3[ci * 16];
            float wa0 = wp[ky0 * 4 + 0], wa1 = wp[ky0 * 4 + 1];
            float wa2 = wp[ky0 * 4 + 2], wa3 = wp[ky0 * 4 + 3];
            float wb0 = wp[(ky0 + 2) * 4 + 0], wb1 = wp[(ky0 + 2) * 4 + 1];
            float wb2 = wp[(ky0 + 2) * 4 + 2], wb3 = wp[(ky0 + 2) * 4 + 3];
#pragma unroll
            for (int s = 0; s < 8; s++) {
                int ia = (s >> 1) + (s & 1) + 1, ib = ia - 1;
                float v = acc[s];
                if (s & 1) {
                    v = fmaf(a[ia],  wa0, v);
                    v = fmaf(a[ib],  wa2, v);
                    v = fmaf(bb[ia], wb0, v);
                    v = fmaf(bb[ib], wb2, v);
                } else {
                    v = fmaf(a[ia],  wa1, v);
                    v = fmaf(a[ib],  wa3, v);
                    v = fmaf(bb[ia], wb1, v);
                    v = fmaf(bb[ib], wb3, v);
                }
                acc[s] = v;
            }
        }
        __syncthreads();
    }

    float b0 = b[0];
    const float* xp = xin + n * 16384 + yo * 128 + x0;
    float* op = out + n * 16384 + yo * 128 + x0;
    float ls = 0.0f;
    float rv[8];
#pragma unroll
    for (int s = 0; s < 8; s++) {
        float r = 1.0f / (1.0f + expf(-(acc[s] + b0)));
        rv[s] = r;
        float df = r - xp[s];
        ls = fmaf(df, df, ls);
    }
    *(float4*)(op)     = make_float4(rv[0], rv[1], rv[2], rv[3]);
    *(float4*)(op + 4) = make_float4(rv[4], rv[5], rv[6], rv[7]);

    red[t] = ls;
    __syncthreads();
    for (int s = 128; s > 0; s >>= 1) {
        if (t < s) red[t] += red[t + s];
        __syncthreads();
    }
    if (t == 0) atomicAdd(out + N_XREC, red[0] * (1.0f / (float)N_XREC));
}

// ---------------- launch ----------------
extern "C" void kernel_launch(void* const* d_in, const int* in_sizes, int n_in,
                              void* d_out, int out_size) {
    const float* x   = (const float*)d_in[0];
    const float* w1  = (const float*)d_in[1];
    const float* b1  = (const float*)d_in[2];
    const float* w2  = (const float*)d_in[3];
    const float* b2  = (const float*)d_in[4];
    const float* w3  = (const float*)d_in[5];
    const float* b3  = (const float*)d_in[6];
    const float* cb  = (const float*)d_in[7];
    const float* dw1 = (const float*)d_in[8];
    const float* db1 = (const float*)d_in[9];
    const float* dw2 = (const float*)d_in[10];
    const float* db2 = (const float*)d_in[11];
    const float* dw3 = (const float*)d_in[12];
    const float* db3 = (const float*)d_in[13];
    float* out = (float*)d_out;

    static bool attr_done = false;
    if (!attr_done) {
        cudaFuncSetAttribute(conv2b_k, cudaFuncAttributeMaxDynamicSharedMemorySize, 28512);
        cudaFuncSetAttribute(conv3x3b_k<0>, cudaFuncAttributeMaxDynamicSharedMemorySize, 31104);
        cudaFuncSetAttribute(conv3x3b_k<1>, cudaFuncAttributeMaxDynamicSharedMemorySize, 31104);
        cudaFuncSetAttribute(deconv2b_k, cudaFuncAttributeMaxDynamicSharedMemorySize, 20736);
        cudaFuncSetAttribute(quantize_m_k, cudaFuncAttributeMaxDynamicSharedMemorySize, 79360);
        attr_done = true;
    }

    prep_all_k <<<348,  256>>>(w3, dw1, w2, dw2, cb, out);
    conv1_k    <<<2048, 256>>>(x, w1, b1);
    conv2b_k   <<<2048, 256, 28512>>>(b2);
    conv3x3b_k<0><<<1024, 256, 31104>>>(b3);
    quantize_m_k<<<1024, 256, 79360>>>(cb, out);
    conv3x3b_k<1><<<1024, 256, 31104>>>(db1);
    deconv2b_k <<<2048, 256, 20736>>>(db2);
    deconv3t_k <<<1024, 256>>>(x, dw3, db3, out);
}

// round 17
// speedup vs baseline: 1.0742x; 1.0581x over previous
#include <cuda_runtime.h>
#include <stdint.h>
#include <math.h>

// ---------------- geometry ----------------
// x      : [128,  1, 128, 128]
// h1b    : [128, 4096hw, 32ci]   conv1 + relu -> bf16         (g_h1b)
// h2b    : [128, 1024hw, 64ci]   conv2 (bf16 mma) -> bf16     (g_h2b)
// z      : [128, 64,  32,  32]   conv3 (bf16 mma) [tf32]      (g_z)
// zqb    : [128, 1024hw, 64ci]   codebook gather -> bf16      (g_zqb)
// d1b    : [128, 1024hw, 64ci]   deconv1 (bf16 mma) -> bf16   (g_d1b)
// d2     : [128, 32,  64,  64]   deconv2 (bf16 mma) fp32      (g_h1)
// x_rec  : [128,  1, 128, 128]   -> d_out[0 : 2097152]
// d_out[2097152] = recon_loss, d_out[2097153] = vq_loss

#define N_XREC   2097152
#define N_Z      8388608

__device__ float    g_h1[128 * 32 * 64 * 64];
__device__ float    g_z [128 * 64 * 32 * 32];
__device__ uint32_t g_h1b[128 * 4096 * 16];
__device__ uint32_t g_h2b[128 * 1024 * 32];
__device__ uint32_t g_zqb[128 * 1024 * 32];
__device__ uint32_t g_d1b[128 * 1024 * 32];
// bf16x2 3x3 weights: [set][sl(4)][tap(9)][kp(8)][72]
__device__ uint32_t g_wtb[2 * 20736];
// bf16x2 conv2 weights: [tap(16)][kp(16)][72]
__device__ uint32_t g_w2b[18432];
// bf16x2 deconv2 weights: [par(4)][tap(4)][kp(32)][40]
__device__ uint32_t g_wd2b[20480];
// tf32-rounded codebook: [k(64)][136]
__device__ float g_cbt[8704];

// ---------------- cp.async helpers ----------------
__device__ __forceinline__ void cp4(uint32_t dst, const float* src, bool p) {
    asm volatile("cp.async.ca.shared.global [%0], [%1], 4, %2;"
                 :: "r"(dst), "l"(src), "r"(p ? 4u : 0u));
}
__device__ __forceinline__ void cp8z(uint32_t dst, const void* src, bool p) {
    asm volatile("cp.async.ca.shared.global [%0], [%1], 8, %2;"
                 :: "r"(dst), "l"(src), "r"(p ? 8u : 0u));
}
__device__ __forceinline__ void cp16(uint32_t dst, const void* src) {
    asm volatile("cp.async.ca.shared.global [%0], [%1], 16;"
                 :: "r"(dst), "l"(src));
}
__device__ __forceinline__ void cp16z(uint32_t dst, const void* src, bool p) {
    asm volatile("cp.async.ca.shared.global [%0], [%1], 16, %2;"
                 :: "r"(dst), "l"(src), "r"(p ? 16u : 0u));
}
__device__ __forceinline__ void cp_commit() {
    asm volatile("cp.async.commit_group;");
}
__device__ __forceinline__ void cp_wait1() {
    asm volatile("cp.async.wait_group 1;");
}
__device__ __forceinline__ void cp_wait0() {
    asm volatile("cp.async.wait_group 0;");
}

// ---------------- mma helpers ----------------
__device__ __forceinline__ uint32_t f2tf(float f) {
    uint32_t r; asm("cvt.rna.tf32.f32 %0, %1;" : "=r"(r) : "f"(f)); return r;
}
__device__ __forceinline__ float f2tf_f(float f) {
    uint32_t r = f2tf(f); return __uint_as_float(r);
}
__device__ __forceinline__ uint32_t pk_bf16(float lo, float hi) {
    uint32_t r; asm("cvt.rn.bf16x2.f32 %0, %1, %2;" : "=r"(r) : "f"(hi), "f"(lo));
    return r;
}
__device__ __forceinline__ void mma_tf32(float& d0, float& d1, float& d2, float& d3,
                                         uint32_t a0, uint32_t a1, uint32_t a2, uint32_t a3,
                                         uint32_t b0, uint32_t b1) {
    asm volatile("mma.sync.aligned.m16n8k8.row.col.f32.tf32.tf32.f32 "
                 "{%0,%1,%2,%3}, {%4,%5,%6,%7}, {%8,%9}, {%0,%1,%2,%3};"
                 : "+f"(d0), "+f"(d1), "+f"(d2), "+f"(d3)
                 : "r"(a0), "r"(a1), "r"(a2), "r"(a3), "r"(b0), "r"(b1));
}
__device__ __forceinline__ void mma_bf16(float& d0, float& d1, float& d2, float& d3,
                                         uint32_t a0, uint32_t a1, uint32_t a2, uint32_t a3,
                                         uint32_t b0, uint32_t b1) {
    asm volatile("mma.sync.aligned.m16n8k16.row.col.f32.bf16.bf16.f32 "
                 "{%0,%1,%2,%3}, {%4,%5,%6,%7}, {%8,%9}, {%0,%1,%2,%3};"
                 : "+f"(d0), "+f"(d1), "+f"(d2), "+f"(d3)
                 : "r"(a0), "r"(a1), "r"(a2), "r"(a3), "r"(b0), "r"(b1));
}

// ---------------- merged prep ----------------
__global__ void __launch_bounds__(256) prep_all_k(const float* __restrict__ w3,
                                                  const float* __restrict__ dw1,
                                                  const float* __restrict__ w2,
                                                  const float* __restrict__ dw2,
                                                  const float* __restrict__ cb,
                                                  float* out) {
    int i = blockIdx.x * 256 + threadIdx.x;
    if (i < 2) { out[N_XREC + i] = 0.0f; }
    if (i < 41472) {
        int set = i / 20736, r = i - set * 20736;
        int o = r % 72, q = r / 72;
        int kp = q & 7, q2 = q >> 3;
        int tap = q2 % 9, sl = q2 / 9;
        int ci0 = sl * 16 + 2 * kp;
        float v0 = 0.0f, v1 = 0.0f;
        if (o < 64) {
            if (set) {
                v0 = dw1[(ci0 * 64 + o) * 9 + (8 - tap)];
                v1 = dw1[((ci0 + 1) * 64 + o) * 9 + (8 - tap)];
            } else {
                v0 = w3[(o * 64 + ci0) * 9 + tap];
                v1 = w3[(o * 64 + ci0 + 1) * 9 + tap];
            }
        }
        g_wtb[i] = pk_bf16(v0, v1);
    } else if (i < 59904) {
        int j = i - 41472;
        int o = j % 72, q = j / 72;
        int kp = q & 15, tap = q >> 4;
        int ci0 = 2 * kp;
        float v0 = 0.0f, v1 = 0.0f;
        if (o < 64) {
            v0 = w2[(o * 32 + ci0) * 16 + tap];
            v1 = w2[(o * 32 + ci0 + 1) * 16 + tap];
        }
        g_w2b[j] = pk_bf16(v0, v1);
    } else if (i < 80384) {
        int j = i - 59904;
        int o = j % 40, q = j / 40;
        int kp = q & 31, q2 = q >> 5;
        int tap = q2 & 3, par = q2 >> 2;
        int py = par >> 1, px = par & 1;
        int ky = (1 - py) + 2 * (tap >> 1);
        int kx = (1 - px) + 2 * (tap & 1);
        int ci0 = 2 * kp;
        float v0 = 0.0f, v1 = 0.0f;
        if (o < 32) {
            v0 = dw2[(ci0 * 32 + o) * 16 + ky * 4 + kx];
            v1 = dw2[((ci0 + 1) * 32 + o) * 16 + ky * 4 + kx];
        }
        g_wd2b[j] = pk_bf16(v0, v1);
    } else if (i < 89088) {
        int j = i - 80384;
        int m = j % 136, k = j / 136;
        float v = 0.0f;
        if (m < 128) v = cb[m * 64 + k];
        g_cbt[j] = f2tf_f(v);
    }
}

// ---------------- conv1: 1->32, k4 s2 p1, relu; output bf16 [hw][ci] ----------------
__global__ void __launch_bounds__(256) conv1_k(const float* __restrict__ x,
                                               const float* __restrict__ w,
                                               const float* __restrict__ b) {
    __shared__ float tin[10][132];
    __shared__ float ws[512];
    __shared__ float bs[32];
    int n = blockIdx.x >> 4, y0 = (blockIdx.x & 15) * 4;
    int t = threadIdx.x;
    int xo = t & 63, ys = t >> 6, yo = y0 + ys;
    for (int i = t; i < 512; i += 256) ws[i] = w[i];
    if (t < 32) bs[t] = b[t];
    const float* xp = x + n * 16384;
    for (int j = t; j < 1320; j += 256) {
        int r = j / 132, c = j - r * 132;
        int iy = 2 * y0 - 1 + r, ix = c - 1;
        float v = 0.0f;
        if ((unsigned)iy < 128u && (unsigned)ix < 128u) v = xp[iy * 128 + ix];
        tin[r][c] = v;
    }
    __syncthreads();

    float xin[16];
#pragma unroll
    for (int ky = 0; ky < 4; ky++)
#pragma unroll
        for (int kx = 0; kx < 4; kx++)
            xin[ky * 4 + kx] = tin[2 * ys + ky][2 * xo + kx];

    float acc[32];
#pragma unroll 4
    for (int o = 0; o < 32; o++) {
        float a = bs[o];
#pragma unroll
        for (int k = 0; k < 16; k++) a = fmaf(xin[k], ws[o * 16 + k], a);
        acc[o] = fmaxf(a, 0.0f);
    }
    uint32_t pk[16];
#pragma unroll
    for (int j = 0; j < 16; j++) pk[j] = pk_bf16(acc[2 * j], acc[2 * j + 1]);
    uint4* op = (uint4*)(g_h1b + (n * 4096 + yo * 64 + xo) * 16);
#pragma unroll
    for (int q = 0; q < 4; q++)
        op[q] = make_uint4(pk[4 * q], pk[4 * q + 1], pk[4 * q + 2], pk[4 * q + 3]);
}

// ---------------- conv2: 32->64, k4 s2 p1, relu — bf16 mma, LDG weights ----------
// smem u32: tinb[6*66 pix][18] = 7128 (28512 B). Zero mainloop barriers. 3 blocks/SM.
__global__ void __launch_bounds__(256, 3) conv2b_k(const float* __restrict__ b) {
    extern __shared__ float dsm[];
    uint32_t* tinb = (uint32_t*)dsm;
    uint32_t tin_s = (uint32_t)__cvta_generic_to_shared(tinb);
    int n = blockIdx.x >> 4, y0 = (blockIdx.x & 15) * 2;
    int t = threadIdx.x;
    int wid = t >> 5, lane = t & 31;
    int g = lane >> 2, tg = lane & 3;
    int obase = (wid & 3) * 16;
    int nbase = (wid >> 2) * 32;
    int o_lo = obase + g, o_hi = o_lo + 8;
    const uint32_t* in0 = g_h1b + n * 65536;

    int boff[4];
#pragma unroll
    for (int nt = 0; nt < 4; nt++) {
        int p = nbase + nt * 8 + g;
        boff[nt] = (p >> 5) * 132 + (p & 31) * 2;
    }

    float acc[4][4];
#pragma unroll
    for (int nt = 0; nt < 4; nt++)
#pragma unroll
        for (int j = 0; j < 4; j++) acc[nt][j] = 0.0f;

    for (int j = t; j < 3168; j += 256) {
        int pix = j >> 3, q = j & 7;
        int r = pix / 66, c = pix - r * 66;
        int iy = 2 * y0 - 1 + r, ix = c - 1;
        bool p = ((unsigned)iy < 64u) & ((unsigned)ix < 64u);
        const uint32_t* src = in0 + (p ? (iy * 64 + ix) * 16 : 0) + q * 2;
        cp8z(tin_s + ((r * 66 + c) * 18 + q * 2) * 4, src, p);
    }
    cp_commit();
    cp_wait0();
    __syncthreads();

#pragma unroll
    for (int tap = 0; tap < 16; tap++) {
        int ky = tap >> 2, kx = tap & 3;
        int doff = ky * 66 + kx;
#pragma unroll
        for (int ks = 0; ks < 2; ks++) {
            const uint32_t* wpb = g_w2b + (tap * 16 + ks * 8) * 72;
            uint32_t ra0 = __ldg(&wpb[tg * 72 + o_lo]);
            uint32_t ra1 = __ldg(&wpb[tg * 72 + o_hi]);
            uint32_t ra2 = __ldg(&wpb[(tg + 4) * 72 + o_lo]);
            uint32_t ra3 = __ldg(&wpb[(tg + 4) * 72 + o_hi]);
#pragma unroll
            for (int nt = 0; nt < 4; nt++) {
                const uint32_t* tp = tinb + (boff[nt] + doff) * 18 + ks * 8;
                uint32_t rb0 = tp[tg];
                uint32_t rb1 = tp[tg + 4];
                mma_bf16(acc[nt][0], acc[nt][1], acc[nt][2], acc[nt][3],
                         ra0, ra1, ra2, ra3, rb0, rb1);
            }
        }
    }

    float bv_lo = b[o_lo], bv_hi = b[o_hi];
    uint32_t* ob = g_h2b + (n * 1024 + y0 * 32) * 32;
#pragma unroll
    for (int nt = 0; nt < 4; nt++) {
#pragma unroll
        for (int c = 0; c < 2; c++) {
            float v0 = fmaxf(acc[nt][c]     + bv_lo, 0.0f);
            float v2 = fmaxf(acc[nt][c + 2] + bv_hi, 0.0f);
            float p0 = __shfl_xor_sync(0xffffffffu, v0, 4);
            float p2 = __shfl_xor_sync(0xffffffffu, v2, 4);
            if (!(g & 1)) {
                int hw = nbase + nt * 8 + tg * 2 + c;
                uint32_t* row = ob + hw * 32;
                row[o_lo >> 1] = pk_bf16(v0, p0);
                row[o_hi >> 1] = pk_bf16(v2, p2);
            }
        }
    }
}

// ---------------- conv3 / deconv1: bf16 mma m2xn4, LDG weights, 3 blocks/SM -------
// smem u32: tinb[216 pix][36] = 7776 (31104 B). Zero mainloop barriers.
template <int SET>
__global__ void __launch_bounds__(256, 3) conv3x3b_k(const float* __restrict__ b) {
    extern __shared__ float dsm[];
    uint32_t* tinb = (uint32_t*)dsm;
    uint32_t tin_s = (uint32_t)__cvta_generic_to_shared(tinb);
    int n = blockIdx.x >> 3, y0 = (blockIdx.x & 7) * 4;
    int t = threadIdx.x;
    int wid = t >> 5, lane = t & 31;
    int g = lane >> 2, tg = lane & 3;
    int obase0 = (wid & 1) * 32;
    int nbase = (wid >> 1) * 32;
    int o_l0 = obase0 + g,      o_h0 = o_l0 + 8;
    int o_l1 = obase0 + 16 + g, o_h1 = o_l1 + 8;
    const uint32_t* in0 = (SET ? g_zqb : g_h2b) + n * 32768;
    const uint32_t* wsrc = g_wtb + SET * 20736;

    int idx0[4];
#pragma unroll
    for (int nt = 0; nt < 4; nt++) {
        int p = nbase + nt * 8 + g;
        idx0[nt] = (p >> 5) * 36 + (p & 31);
    }

    float acc[2][4][4];
#pragma unroll
    for (int m2 = 0; m2 < 2; m2++)
#pragma unroll
        for (int nt = 0; nt < 4; nt++)
#pragma unroll
            for (int j = 0; j < 4; j++) acc[m2][nt][j] = 0.0f;

    for (int j = t; j < 1632; j += 256) {
        int pix = j >> 3, q = j & 7;
        int r = pix / 34, c = pix - r * 34;
        int iy = y0 - 1 + r, ix = c - 1;
        bool p = ((unsigned)iy < 32u) & ((unsigned)ix < 32u);
        const uint32_t* src = in0 + (p ? (iy * 32 + ix) * 32 : 0) + q * 4;
        cp16z(tin_s + ((r * 36 + c) * 36 + q * 4) * 4, src, p);
    }
    cp_commit();

    // register-pipelined weight prefetch: fragments for iteration it+1 load
    // while iteration it's mma chain runs. 36 iterations (sl*9 + tap), no barriers.
    const uint32_t* wpb0 = wsrc;
    uint32_t c00 = __ldg(&wpb0[tg * 72 + o_l0]);
    uint32_t c01 = __ldg(&wpb0[tg * 72 + o_h0]);
    uint32_t c02 = __ldg(&wpb0[(tg + 4) * 72 + o_l0]);
    uint32_t c03 = __ldg(&wpb0[(tg + 4) * 72 + o_h0]);
    uint32_t c10 = __ldg(&wpb0[tg * 72 + o_l1]);
    uint32_t c11 = __ldg(&wpb0[tg * 72 + o_h1]);
    uint32_t c12 = __ldg(&wpb0[(tg + 4) * 72 + o_l1]);
    uint32_t c13 = __ldg(&wpb0[(tg + 4) * 72 + o_h1]);

    cp_wait0();
    __syncthreads();

#pragma unroll
    for (int it = 0; it < 36; it++) {
        int sl = it / 9, tap = it - sl * 9;
        int ky = tap / 3, kx = tap - ky * 3;
        int koff = sl * 8;
        int doff = ky * 36 + kx;
        uint32_t a00 = c00, a01 = c01, a02 = c02, a03 = c03;
        uint32_t a10 = c10, a11 = c11, a12 = c12, a13 = c13;
        if (it < 35) {
            const uint32_t* wpb = wsrc + (it + 1) * 576;
            c00 = __ldg(&wpb[tg * 72 + o_l0]);
            c01 = __ldg(&wpb[tg * 72 + o_h0]);
            c02 = __ldg(&wpb[(tg + 4) * 72 + o_l0]);
            c03 = __ldg(&wpb[(tg + 4) * 72 + o_h0]);
            c10 = __ldg(&wpb[tg * 72 + o_l1]);
            c11 = __ldg(&wpb[tg * 72 + o_h1]);
            c12 = __ldg(&wpb[(tg + 4) * 72 + o_l1]);
            c13 = __ldg(&wpb[(tg + 4) * 72 + o_h1]);
        }
#pragma unroll
        for (int nt = 0; nt < 4; nt++) {
            const uint32_t* tp = tinb + (idx0[nt] + doff) * 36 + koff;
            uint32_t rb0 = tp[tg];
            uint32_t rb1 = tp[tg + 4];
            mma_bf16(acc[0][nt][0], acc[0][nt][1], acc[0][nt][2], acc[0][nt][3],
                     a00, a01, a02, a03, rb0, rb1);
            mma_bf16(acc[1][nt][0], acc[1][nt][1], acc[1][nt][2], acc[1][nt][3],
                     a10, a11, a12, a13, rb0, rb1);
        }
    }

    if (SET == 0) {
        float* outbase = g_z + n * 65536 + y0 * 32;
#pragma unroll
        for (int m2 = 0; m2 < 2; m2++) {
            int olo = obase0 + m2 * 16 + g, ohi = olo + 8;
            float bl = b[olo], bh = b[ohi];
#pragma unroll
            for (int nt = 0; nt < 4; nt++) {
                int pc = nbase + nt * 8 + tg * 2;
                *(float2*)(outbase + olo * 1024 + pc) =
                    make_float2(f2tf_f(acc[m2][nt][0] + bl), f2tf_f(acc[m2][nt][1] + bl));
                *(float2*)(outbase + ohi * 1024 + pc) =
                    make_float2(f2tf_f(acc[m2][nt][2] + bh), f2tf_f(acc[m2][nt][3] + bh));
            }
        }
    } else {
        uint32_t* ob = g_d1b + (n * 1024 + y0 * 32) * 32;
#pragma unroll
        for (int m2 = 0; m2 < 2; m2++) {
            int olo = obase0 + m2 * 16 + g, ohi = olo + 8;
            float bl = b[olo], bh = b[ohi];
#pragma unroll
            for (int nt = 0; nt < 4; nt++) {
                float v0 = fmaxf(acc[m2][nt][0] + bl, 0.0f);
                float v1 = fmaxf(acc[m2][nt][1] + bl, 0.0f);
                float v2 = fmaxf(acc[m2][nt][2] + bh, 0.0f);
                float v3 = fmaxf(acc[m2][nt][3] + bh, 0.0f);
                float p0 = __shfl_xor_sync(0xffffffffu, v0, 4);
                float p1 = __shfl_xor_sync(0xffffffffu, v1, 4);
                float p2 = __shfl_xor_sync(0xffffffffu, v2, 4);
                float p3 = __shfl_xor_sync(0xffffffffu, v3, 4);
                if (!(g & 1)) {
                    int pc = nbase + nt * 8 + tg * 2;
                    uint32_t* r0 = ob + pc * 32;
                    uint32_t* r1 = r0 + 32;
                    r0[olo >> 1] = pk_bf16(v0, p0);
                    r1[olo >> 1] = pk_bf16(v1, p1);
                    r0[ohi >> 1] = pk_bf16(v2, p2);
                    r1[ohi >> 1] = pk_bf16(v3, p3);
                }
            }
        }
    }
}

// ---------------- quantize — tf32 mma GEMM + argmin (z pre-rounded tf32) ----------
__global__ void __launch_bounds__(256) quantize_m_k(const float* __restrict__ cb,
                                                    float* out) {
    extern __shared__ float dsm[];
    float* zt   = dsm;
    float* cbt  = dsm + 8704;
    float* minS = dsm + 17408;
    int*   minI = (int*)(dsm + 18432);
    float* cn   = dsm + 19456;
    float* red  = dsm + 19584;
    uint32_t zt_s  = (uint32_t)__cvta_generic_to_shared(zt);
    uint32_t cbt_s = (uint32_t)__cvta_generic_to_shared(cbt);
    int t = threadIdx.x;
    int n = blockIdx.x >> 3, hw0 = (blockIdx.x & 7) * 128;
    int wid = t >> 5, lane = t & 31;
    int g = lane >> 2, tg = lane & 3;
    int mbase = wid * 16;

    const float* zsrc = g_z + n * 65536 + hw0;
    for (int j = t; j < 2048; j += 256) {
        int row = j >> 5, c4 = j & 31;
        cp16(zt_s + (row * 136 + c4 * 4) * 4, zsrc + row * 1024 + c4 * 4);
    }
    for (int j = t; j < 2176; j += 256)
        cp16(cbt_s + j * 16, g_cbt + j * 4);
    cp_commit();
    if (t < 128) {
        float s = 0.0f;
        const float* cp = cb + t * 64;
#pragma unroll
        for (int d = 0; d < 64; d++) s = fmaf(cp[d], cp[d], s);
        cn[t] = s;
    }
    cp_wait0();
    __syncthreads();

    float acc[16][4];
#pragma unroll
    for (int nt = 0; nt < 16; nt++)
#pragma unroll
        for (int j = 0; j < 4; j++) acc[nt][j] = 0.0f;

#pragma unroll
    for (int ks = 0; ks < 8; ks++) {
        const float* a0 = cbt + (ks * 8 + tg) * 136 + mbase + g;
        const float* a1 = cbt + (ks * 8 + tg + 4) * 136 + mbase + g;
        uint32_t ra0 = *(const uint32_t*)a0;
        uint32_t ra1 = *(const uint32_t*)(a0 + 8);
        uint32_t ra2 = *(const uint32_t*)a1;
        uint32_t ra3 = *(const uint32_t*)(a1 + 8);
        const float* b0 = zt + (ks * 8 + tg) * 136 + g;
        const float* b1 = zt + (ks * 8 + tg + 4) * 136 + g;
#pragma unroll
        for (int nt = 0; nt < 16; nt++) {
            uint32_t rb0 = *(const uint32_t*)&b0[nt * 8];
            uint32_t rb1 = *(const uint32_t*)&b1[nt * 8];
            mma_tf32(acc[nt][0], acc[nt][1], acc[nt][2], acc[nt][3],
                     ra0, ra1, ra2, ra3, rb0, rb1);
        }
    }

    float cn_lo = cn[mbase + g], cn_hi = cn[mbase + g + 8];
#pragma unroll
    for (int nt = 0; nt < 16; nt++) {
#pragma unroll
        for (int c2 = 0; c2 < 2; c2++) {
            float s_lo = fmaf(-2.0f, acc[nt][c2],     cn_lo);
            float s_hi = fmaf(-2.0f, acc[nt][c2 + 2], cn_hi);
            float s = s_lo; int idx = mbase + g;
            if (s_hi < s) { s = s_hi; idx = mbase + g + 8; }
#pragma unroll
            for (int m = 4; m <= 16; m <<= 1) {
                float so = __shfl_xor_sync(0xffffffffu, s, m);
                int   io = __shfl_xor_sync(0xffffffffu, idx, m);
                if (so < s || (so == s && io < idx)) { s = so; idx = io; }
            }
            if (g == 0) {
                int px = nt * 8 + tg * 2 + c2;
                minS[wid * 128 + px] = s;
                minI[wid * 128 + px] = idx;
            }
        }
    }
    __syncthreads();

    int px = t & 127, half = t >> 7;
    float bs = minS[px]; int bi = minI[px];
#pragma unroll
    for (int w = 1; w < 8; w++) {
        float s = minS[w * 128 + px]; int i2 = minI[w * 128 + px];
        if (s < bs || (s == bs && i2 < bi)) { bs = s; bi = i2; }
    }
    float vs = 0.0f;
    const float* cbp = cb + bi * 64 + half * 32;
    uint32_t* zq32 = g_zqb + (n * 1024 + hw0 + px) * 32 + half * 16;
#pragma unroll
    for (int d2 = 0; d2 < 16; d2++) {
        float c0 = cbp[2 * d2], c1 = cbp[2 * d2 + 1];
        zq32[d2] = pk_bf16(c0, c1);
        float df0 = zt[(half * 32 + 2 * d2) * 136 + px] - c0;
        float df1 = zt[(half * 32 + 2 * d2 + 1) * 136 + px] - c1;
        vs = fmaf(df0, df0, vs);
        vs = fmaf(df1, df1, vs);
    }
    red[t] = vs;
    __syncthreads();
    for (int s = 128; s > 0; s >>= 1) {
        if (t < s) red[t] += red[t + s];
        __syncthreads();
    }
    if (t == 0) atomicAdd(out + N_XREC + 1, red[0] * (1.0f / (float)N_Z));
}

// ---------------- deconv2: bf16 mma parity GEMM, LDG weights, 3 blocks/SM --------
// smem u32: tinb[4*36 pix][36] = 5184 (20736 B). Zero mainloop barriers.
__global__ void __launch_bounds__(256, 3) deconv2b_k(const float* __restrict__ b) {
    extern __shared__ float dsm[];
    uint32_t* tinb = (uint32_t*)dsm;
    uint32_t tin_s = (uint32_t)__cvta_generic_to_shared(tinb);
    int n = blockIdx.x >> 4, u0 = (blockIdx.x & 15) * 2;
    int t = threadIdx.x;
    int wid = t >> 5, lane = t & 31;
    int g = lane >> 2, tg = lane & 3;
    int half = wid & 1, par = wid >> 1;
    int py = par >> 1, px = par & 1;
    int o_l0 = g, o_h0 = g + 8, o_l1 = g + 16, o_h1 = g + 24;
    const uint32_t* in0 = g_d1b + n * 32768;

    int boff[4];
#pragma unroll
    for (int nt = 0; nt < 4; nt++) {
        int p = half * 32 + nt * 8 + g;
        boff[nt] = (p >> 5) * 36 + (p & 31);
    }

    float acc[2][4][4];
#pragma unroll
    for (int m2 = 0; m2 < 2; m2++)
#pragma unroll
        for (int nt = 0; nt < 4; nt++)
#pragma unroll
            for (int j = 0; j < 4; j++) acc[m2][nt][j] = 0.0f;

    for (int j = t; j < 1088; j += 256) {
        int pix = j >> 3, q = j & 7;
        int r = pix / 34, c = pix - r * 34;
        int yi = u0 - 1 + r, xi = c - 1;
        bool p = ((unsigned)yi < 32u) & ((unsigned)xi < 32u);
        const uint32_t* src = in0 + (p ? (yi * 32 + xi) * 32 : 0) + q * 4;
        cp16z(tin_s + ((r * 36 + c) * 36 + q * 4) * 4, src, p);
    }
    cp_commit();

    const uint32_t* wp0 = g_wd2b + par * 5120;     // [tap(4)][kp(32)][40]
    uint32_t c00 = __ldg(&wp0[tg * 40 + o_l0]);
    uint32_t c01 = __ldg(&wp0[tg * 40 + o_h0]);
    uint32_t c02 = __ldg(&wp0[(tg + 4) * 40 + o_l0]);
    uint32_t c03 = __ldg(&wp0[(tg + 4) * 40 + o_h0]);
    uint32_t c10 = __ldg(&wp0[tg * 40 + o_l1]);
    uint32_t c11 = __ldg(&wp0[tg * 40 + o_h1]);
    uint32_t c12 = __ldg(&wp0[(tg + 4) * 40 + o_l1]);
    uint32_t c13 = __ldg(&wp0[(tg + 4) * 40 + o_h1]);

    cp_wait0();
    __syncthreads();

#pragma unroll
    for (int it = 0; it < 16; it++) {
        int tap = it >> 2, ks = it & 3;
        int jj = tap >> 1, ii = tap & 1;
        int dy = py - jj, dx = px - ii;
        int doff = (1 + dy) * 36 + (1 + dx);
        uint32_t a00 = c00, a01 = c01, a02 = c02, a03 = c03;
        uint32_t a10 = c10, a11 = c11, a12 = c12, a13 = c13;
        if (it < 15) {
            int it2 = it + 1;
            const uint32_t* wpb = wp0 + (it2 >> 2) * 1280 + (it2 & 3) * 320;
            c00 = __ldg(&wpb[tg * 40 + o_l0]);
            c01 = __ldg(&wpb[tg * 40 + o_h0]);
            c02 = __ldg(&wpb[(tg + 4) * 40 + o_l0]);
            c03 = __ldg(&wpb[(tg + 4) * 40 + o_h0]);
            c10 = __ldg(&wpb[tg * 40 + o_l1]);
            c11 = __ldg(&wpb[tg * 40 + o_h1]);
            c12 = __ldg(&wpb[(tg + 4) * 40 + o_l1]);
            c13 = __ldg(&wpb[(tg + 4) * 40 + o_h1]);
        }
#pragma unroll
        for (int nt = 0; nt < 4; nt++) {
            const uint32_t* tp = tinb + (boff[nt] + doff) * 36 + ks * 8;
            uint32_t rb0 = tp[tg];
            uint32_t rb1 = tp[tg + 4];
            mma_bf16(acc[0][nt][0], acc[0][nt][1], acc[0][nt][2], acc[0][nt][3],
                     a00, a01, a02, a03, rb0, rb1);
            mma_bf16(acc[1][nt][0], acc[1][nt][1], acc[1][nt][2], acc[1][nt][3],
                     a10, a11, a12, a13, rb0, rb1);
        }
    }

    float* ob = g_h1 + n * 131072;
#pragma unroll
    for (int m2 = 0; m2 < 2; m2++) {
        int olo = m2 * 16 + g, ohi = olo + 8;
        float bl = b[olo], bh = b[ohi];
#pragma unroll
        for (int nt = 0; nt < 4; nt++) {
#pragma unroll
            for (int c2 = 0; c2 < 2; c2++) {
                int np = half * 32 + nt * 8 + tg * 2 + c2;
                int u_l = np >> 5, v = np & 31;
                int yo = 2 * (u0 + u_l) + py, xo = 2 * v + px;
                ob[olo * 4096 + yo * 64 + xo] = fmaxf(acc[m2][nt][c2]     + bl, 0.0f);
                ob[ohi * 4096 + yo * 64 + xo] = fmaxf(acc[m2][nt][c2 + 2] + bh, 0.0f);
            }
        }
    }
}

// ---------------- deconv3: 32->1, k4 s2 p1, sigmoid + recon loss ----------------
__global__ void __launch_bounds__(256) deconv3t_k(const float* __restrict__ xin,
                                                  const float* __restrict__ w,
                                                  const float* __restrict__ b,
                                                  float* out) {
    __shared__ float tin[2][8][10][66];
    __shared__ float ws3[512];
    __shared__ float red[256];
    uint32_t tin_s = (uint32_t)__cvta_generic_to_shared(&tin[0][0][0][0]);
    int n = blockIdx.x >> 3, y0 = (blockIdx.x & 7) * 16;
    int t = threadIdx.x;
    int ys = t >> 4, x0 = (t & 15) * 8;
    int yo = y0 + ys;
    int ky0 = (yo + 1) & 1;
    int yiA = (yo + 1 - ky0) >> 1;
    int rowA = yiA - (y0 >> 1) + 1;
    int rowB = rowA - 1;
    int cbase = x0 >> 1;

    for (int j = t; j < 512; j += 256) ws3[j] = w[j];

    float acc[8];
#pragma unroll
    for (int s = 0; s < 8; s++) acc[s] = 0.0f;

    const float* in0 = g_h1 + n * 131072;
    auto load_chunk = [&](int buf, int ch) {
        for (int j = t; j < 5280; j += 256) {
            int cc = j / 660, rem = j - cc * 660, r = rem / 66, c = rem - r * 66;
            int yi = (y0 >> 1) - 1 + r, xi = c - 1;
            bool p = ((unsigned)yi < 64u) & ((unsigned)xi < 64u);
            const float* src = in0 + (ch * 8 + cc) * 4096 + (p ? yi * 64 + xi : 0);
            cp4(tin_s + (buf * 5280 + j) * 4, src, p);
        }
        cp_commit();
    };

    load_chunk(0, 0);
    for (int ch = 0; ch < 4; ch++) {
        if (ch < 3) { load_chunk((ch + 1) & 1, ch + 1); cp_wait1(); }
        else        { cp_wait0(); }
        __syncthreads();
        int buf = ch & 1;
#pragma unroll 2
        for (int cc = 0; cc < 8; cc++) {
            float a[6], bb[6];
#pragma unroll
            for (int c = 0; c < 6; c++) {
                a[c]  = tin[buf][cc][rowA][cbase + c];
                bb[c] = tin[buf][cc][rowB][cbase + c];
            }
            int ci = ch * 8 + cc;
            const float* wp = &ws3[ci * 16];
            float wa0 = wp[ky0 * 4 + 0], wa1 = wp[ky0 * 4 + 1];
            float wa2 = wp[ky0 * 4 + 2], wa3 = wp[ky0 * 4 + 3];
            float wb0 = wp[(ky0 + 2) * 4 + 0], wb1 = wp[(ky0 + 2) * 4 + 1];
            float wb2 = wp[(ky0 + 2) * 4 + 2], wb3 = wp[(ky0 + 2) * 4 + 3];
#pragma unroll
            for (int s = 0; s < 8; s++) {
                int ia = (s >> 1) + (s & 1) + 1, ib = ia - 1;
                float v = acc[s];
                if (s & 1) {
                    v = fmaf(a[ia],  wa0, v);
                    v = fmaf(a[ib],  wa2, v);
                    v = fmaf(bb[ia], wb0, v);
                    v = fmaf(bb[ib], wb2, v);
                } else {
                    v = fmaf(a[ia],  wa1, v);
                    v = fmaf(a[ib],  wa3, v);
                    v = fmaf(bb[ia], wb1, v);
                    v = fmaf(bb[ib], wb3, v);
                }
                acc[s] = v;
            }
        }
        __syncthreads();
    }

    float b0 = b[0];
    const float* xp = xin + n * 16384 + yo * 128 + x0;
    float* op = out + n * 16384 + yo * 128 + x0;
    float ls = 0.0f;
    float rv[8];
#pragma unroll
    for (int s = 0; s < 8; s++) {
        float r = 1.0f / (1.0f + expf(-(acc[s] + b0)));
        rv[s] = r;
        float df = r - xp[s];
        ls = fmaf(df, df, ls);
    }
    *(float4*)(op)     = make_float4(rv[0], rv[1], rv[2], rv[3]);
    *(float4*)(op + 4) = make_float4(rv[4], rv[5], rv[6], rv[7]);

    red[t] = ls;
    __syncthreads();
    for (int s = 128; s > 0; s >>= 1) {
        if (t < s) red[t] += red[t + s];
        __syncthreads();
    }
    if (t == 0) atomicAdd(out + N_XREC, red[0] * (1.0f / (float)N_XREC));
}

// ---------------- launch ----------------
extern "C" void kernel_launch(void* const* d_in, const int* in_sizes, int n_in,
                              void* d_out, int out_size) {
    const float* x   = (const float*)d_in[0];
    const float* w1  = (const float*)d_in[1];
    const float* b1  = (const float*)d_in[2];
    const float* w2  = (const float*)d_in[3];
    const float* b2  = (const float*)d_in[4];
    const float* w3  = (const float*)d_in[5];
    const float* b3  = (const float*)d_in[6];
    const float* cb  = (const float*)d_in[7];
    const float* dw1 = (const float*)d_in[8];
    const float* db1 = (const float*)d_in[9];
    const float* dw2 = (const float*)d_in[10];
    const float* db2 = (const float*)d_in[11];
    const float* dw3 = (const float*)d_in[12];
    const float* db3 = (const float*)d_in[13];
    float* out = (float*)d_out;

    static bool attr_done = false;
    if (!attr_done) {
        cudaFuncSetAttribute(conv2b_k, cudaFuncAttributeMaxDynamicSharedMemorySize, 28512);
        cudaFuncSetAttribute(conv3x3b_k<0>, cudaFuncAttributeMaxDynamicSharedMemorySize, 31104);
        cudaFuncSetAttribute(conv3x3b_k<1>, cudaFuncAttributeMaxDynamicSharedMemorySize, 31104);
        cudaFuncSetAttribute(deconv2b_k, cudaFuncAttributeMaxDynamicSharedMemorySize, 20736);
        cudaFuncSetAttribute(quantize_m_k, cudaFuncAttributeMaxDynamicSharedMemorySize, 79360);
        attr_done = true;
    }

    prep_all_k <<<348,  256>>>(w3, dw1, w2, dw2, cb, out);
    conv1_k    <<<2048, 256>>>(x, w1, b1);
    conv2b_k   <<<2048, 256, 28512>>>(b2);
    conv3x3b_k<0><<<1024, 256, 31104>>>(b3);
    quantize_m_k<<<1024, 256, 79360>>>(cb, out);
    conv3x3b_k<1><<<1024, 256, 31104>>>(db1);
    deconv2b_k <<<2048, 256, 20736>>>(db2);
    deconv3t_k <<<1024, 256>>>(x, dw3, db3, out);
}